// round 12
// baseline (speedup 1.0000x reference)
#include <cuda_runtime.h>
#include <cuda_fp16.h>
#include <math.h>
#include <stdint.h>

#define B_    512
#define E_    1024
#define ML_   50
#define V_    50000
#define G4E_  (4*E_)
#define NPADV 50048          // V padded to multiple of 128
#define KGATE 2048           // gates K: [words|ctx] vs [w_ih|w_hh]

// ---------------- scratch (__device__ globals; allocation-free rule) --------
__device__ float g_ctx[B_*E_];
__device__ float g_gates[(long long)B_*G4E_];
__device__ int   g_pad_byte_mode;

__device__ __half g_wp[(long long)NPADV*E_];     // w_proj fp16 (rows >= V_ zero)
__device__ __half g_wg[(long long)G4E_*KGATE];   // [w_ih | w_hh] fp16
__device__ __half g_ag[B_*KGATE];                // [words | ctx] fp16 (GEMM A)
__device__ __half g_h[B_*E_];                    // h_new fp16 (GEMM A)

union H8 { __half h[8]; uint4 u; };

// ---------------- PTX helpers (arch-stable, sm_80-era) ----------------------
__device__ __forceinline__ uint32_t smem_u32(const void* p) {
    uint32_t a;
    asm("{ .reg .u64 t; cvta.to.shared.u64 t, %1; cvt.u32.u64 %0, t; }" : "=r"(a) : "l"(p));
    return a;
}
#define CP_ASYNC16(dst, src) \
    asm volatile("cp.async.cg.shared.global [%0], [%1], 16;" :: "r"(dst), "l"(src) : "memory")
#define CP_COMMIT() asm volatile("cp.async.commit_group;" ::: "memory")
#define CP_WAIT1()  asm volatile("cp.async.wait_group 1;" ::: "memory")
#define CP_WAIT0()  asm volatile("cp.async.wait_group 0;" ::: "memory")

__device__ __forceinline__ void ldsm_x4(uint32_t addr, uint32_t& r0, uint32_t& r1,
                                        uint32_t& r2, uint32_t& r3) {
    asm volatile("ldmatrix.sync.aligned.m8n8.x4.shared.b16 {%0,%1,%2,%3}, [%4];"
                 : "=r"(r0), "=r"(r1), "=r"(r2), "=r"(r3) : "r"(addr));
}
__device__ __forceinline__ void mma16816(float* c, const uint32_t* a, const uint32_t* b) {
    asm volatile("mma.sync.aligned.m16n8k16.row.col.f32.f16.f16.f32 "
                 "{%0,%1,%2,%3}, {%4,%5,%6,%7}, {%8,%9}, {%0,%1,%2,%3};"
                 : "+f"(c[0]), "+f"(c[1]), "+f"(c[2]), "+f"(c[3])
                 : "r"(a[0]), "r"(a[1]), "r"(a[2]), "r"(a[3]), "r"(b[0]), "r"(b[1]));
}
__device__ __forceinline__ uint32_t swz128(uint32_t o) { return o ^ ((o >> 3) & 0x70); }

// ---------------------------------------------------------------------------
// pad dtype detect (robust: bool-as-byte vs int32/float32 0/1)
// ---------------------------------------------------------------------------
__global__ void detect_pad_kernel(const unsigned char* __restrict__ pad) {
    __shared__ int s_gt1, s_off4;
    if (threadIdx.x == 0) { s_gt1 = 0; s_off4 = 0; }
    __syncthreads();
    for (int i = threadIdx.x; i < B_*ML_; i += blockDim.x) {
        unsigned char v = pad[i];
        if (v > 1) atomicOr(&s_gt1, 1);
        if (v != 0 && (i & 3) != 0) atomicOr(&s_off4, 1);
    }
    __syncthreads();
    if (threadIdx.x == 0)
        g_pad_byte_mode = (s_gt1 == 0 && s_off4 != 0) ? 1 : 0;
}

// ---------------------------------------------------------------------------
// Embedding gather -> fp16 A cols [0,1024), 4 elems/thread (SIDE stream)
// ---------------------------------------------------------------------------
__global__ void gather_words_kernel(const int* __restrict__ tgt,
                                    const float* __restrict__ emb) {
    int t = blockIdx.x * blockDim.x + threadIdx.x;
    if (t >= B_*(E_/4)) return;
    int b = t / (E_/4), e4 = t % (E_/4);
    float4 v = *(const float4*)(emb + (long long)tgt[b] * E_ + e4*4);
    __half2 h01 = __floats2half2_rn(v.x, v.y);
    __half2 h23 = __floats2half2_rn(v.z, v.w);
    uint2 u = make_uint2(*(uint32_t*)&h01, *(uint32_t*)&h23);
    *(uint2*)&g_ag[b * KGATE + e4*4] = u;
}

// ---------------------------------------------------------------------------
// Single-read attention: the full 50x1024 fp32 enc tile is staged in 200 KB
// of dynamic smem via cp.async; energies, softmax, context all read smem.
// 512 threads; one block per batch row.
// ---------------------------------------------------------------------------
__global__ void __launch_bounds__(512, 1) attn_fused_kernel(
    const float* __restrict__ enc,
    const float* __restrict__ h0,
    const void* __restrict__ pad_raw)
{
    extern __shared__ float s_enc[];            // [ML_ * E_] = 200 KB
    __shared__ float4 sh_h4[E_/4];
    __shared__ float  sh_w[ML_];

    int b = blockIdx.x;
    int tid = threadIdx.x;
    const uint32_t s_enc_u = smem_u32(s_enc);

    // stage enc tile: 204800 B = 12800 x 16B, 25 ops/thread
    {
        const float* src = enc + (long long)b * ML_ * E_;
        #pragma unroll
        for (int j = 0; j < 25; j++) {
            int op = tid + j * 512;
            CP_ASYNC16(s_enc_u + op * 16, (const void*)(src + op * 4));
        }
        CP_COMMIT();
    }
    if (tid < E_/4) sh_h4[tid] = ((const float4*)(h0 + (long long)b*E_))[tid];
    CP_WAIT0();
    __syncthreads();

    // energies: warp w handles rows w, w+16, w+32
    int w = tid >> 5, lane = tid & 31;
    for (int l = w; l < ML_; l += 16) {
        const float4* row4 = (const float4*)(s_enc + l * E_);
        float s = 0.f;
        #pragma unroll
        for (int j = 0; j < 8; j++) {
            float4 x = row4[lane + j*32];
            float4 h = sh_h4[lane + j*32];
            s += x.x*h.x + x.y*h.y + x.z*h.z + x.w*h.w;
        }
        #pragma unroll
        for (int o = 16; o > 0; o >>= 1) s += __shfl_down_sync(0xffffffffu, s, o);
        if (lane == 0) sh_w[l] = s;
    }
    __syncthreads();

    if (tid == 0) {
        int bm = g_pad_byte_mode;
        const unsigned char* p8 = (const unsigned char*)pad_raw;
        const unsigned int*  pw = (const unsigned int*)pad_raw;
        float mx = -1e30f;
        for (int l = 0; l < ML_; l++) mx = fmaxf(mx, sh_w[l]);
        float sum = 0.f;
        for (int l = 0; l < ML_; l++) {
            bool masked = bm ? (p8[b*ML_ + l] != 0) : (pw[b*ML_ + l] != 0u);
            float v = masked ? 0.f : __expf(sh_w[l] - mx);
            sh_w[l] = v; sum += v;
        }
        float inv = 1.f / sum;
        for (int l = 0; l < ML_; l++) sh_w[l] *= inv;
    }
    __syncthreads();

    // context: thread -> 2 columns (512 x 2 = 1024)
    {
        int col = tid * 2;
        float a0 = 0.f, a1 = 0.f;
        #pragma unroll 10
        for (int l = 0; l < ML_; l++) {
            float wl = sh_w[l];
            float2 v = *(const float2*)(s_enc + l * E_ + col);
            a0 += wl * v.x; a1 += wl * v.y;
        }
        *(float2*)(g_ctx + (long long)b*E_ + col) = make_float2(a0, a1);
        __half2 hc = __floats2half2_rn(a0, a1);
        *(uint32_t*)&g_ag[b * KGATE + E_ + col] = *(uint32_t*)&hc;
    }
}

// ---------------------------------------------------------------------------
// fp32 -> fp16 weight converters (SIDE stream, overlapped)
// ---------------------------------------------------------------------------
__global__ void conv_wproj_kernel(const float* __restrict__ src) {
    long long t = (long long)blockIdx.x * blockDim.x + threadIdx.x;
    const long long total = (long long)NPADV * (E_/8);
    if (t >= total) return;
    int row = (int)(t / (E_/8));
    int k0  = (int)(t % (E_/8)) * 8;
    H8 hi;
    if (row < V_) {
        const float4 a = *(const float4*)(src + (long long)row*E_ + k0);
        const float4 b = *(const float4*)(src + (long long)row*E_ + k0 + 4);
        hi.h[0]=__float2half_rn(a.x); hi.h[1]=__float2half_rn(a.y);
        hi.h[2]=__float2half_rn(a.z); hi.h[3]=__float2half_rn(a.w);
        hi.h[4]=__float2half_rn(b.x); hi.h[5]=__float2half_rn(b.y);
        hi.h[6]=__float2half_rn(b.z); hi.h[7]=__float2half_rn(b.w);
    } else {
        hi.u = make_uint4(0u, 0u, 0u, 0u);
    }
    *(uint4*)&g_wp[(long long)row * E_ + k0] = hi.u;
}

__global__ void conv_wgate_kernel(const float* __restrict__ w_ih,
                                  const float* __restrict__ w_hh) {
    long long t = (long long)blockIdx.x * blockDim.x + threadIdx.x;
    const long long total = (long long)G4E_ * (KGATE/8);
    if (t >= total) return;
    int row = (int)(t / (KGATE/8));
    int k0  = (int)(t % (KGATE/8)) * 8;
    const float* s = (k0 < E_) ? (w_ih + (long long)row*E_ + k0)
                               : (w_hh + (long long)row*E_ + (k0 - E_));
    const float4 a = *(const float4*)s;
    const float4 b = *(const float4*)(s + 4);
    H8 hi;
    hi.h[0]=__float2half_rn(a.x); hi.h[1]=__float2half_rn(a.y);
    hi.h[2]=__float2half_rn(a.z); hi.h[3]=__float2half_rn(a.w);
    hi.h[4]=__float2half_rn(b.x); hi.h[5]=__float2half_rn(b.y);
    hi.h[6]=__float2half_rn(b.z); hi.h[7]=__float2half_rn(b.w);
    *(uint4*)&g_wg[(long long)row * KGATE + k0] = hi.u;
}

// ---------------------------------------------------------------------------
// fp16 GEMM via mma.sync (proven): C[M,N] = A[M,K2] * B[N,K2]^T (+bias)
// CTA BMx128, K-chunk 64, 3-stage cp.async pipeline, SW128 smem, ldmatrix.
// ---------------------------------------------------------------------------
template<int BM>
__global__ void __launch_bounds__(256, 2) gemm_fp16_mma(
    const __half* __restrict__ A2, const __half* __restrict__ B2,
    float* __restrict__ C, const float* __restrict__ bias,
    int K2, int Nreal)
{
    constexpr int WMW = (BM == 128) ? 4 : 2;
    constexpr int WNW = 8 / WMW;
    constexpr int WN  = 128 / WNW;
    constexpr int NT  = WN / 8;
    constexpr int ATILE = BM * 128;
    constexpr int STAGE = ATILE + 16384;
    constexpr int OPS = (BM + 128) / 32;
    constexpr int OPSA = BM * 8;

    extern __shared__ char smem_raw[];
    const uint32_t smem = smem_u32(smem_raw);

    const int tid = threadIdx.x;
    const int wid = tid >> 5, lane = tid & 31;
    const int wm = wid % WMW, wn = wid / WMW;
    const int m0 = blockIdx.x * BM, n0 = blockIdx.y * 128;
    const int nch = K2 >> 6;

    const __half* Abase = A2 + (long long)m0 * K2;
    const __half* Bbase = B2 + (long long)n0 * K2;

    auto issue_stage = [&](int stage, int chunk) {
        int kc = chunk * 64;
        uint32_t sbase = smem + stage * STAGE;
        #pragma unroll
        for (int j = 0; j < OPS; j++) {
            int op = tid + j * 256;
            const __half* src;
            uint32_t dst;
            if (op < OPSA) {
                int row = op >> 3, c = op & 7;
                src = Abase + (long long)row * K2 + kc + c * 8;
                dst = sbase + swz128((uint32_t)(row * 128 + c * 16));
            } else {
                int op2 = op - OPSA;
                int row = op2 >> 3, c = op2 & 7;
                src = Bbase + (long long)row * K2 + kc + c * 8;
                dst = sbase + ATILE + swz128((uint32_t)(row * 128 + c * 16));
            }
            CP_ASYNC16(dst, (const void*)src);
        }
        CP_COMMIT();
    };

    float acc[2][NT][4];
    #pragma unroll
    for (int mt = 0; mt < 2; mt++)
        #pragma unroll
        for (int nt = 0; nt < NT; nt++)
            #pragma unroll
            for (int q = 0; q < 4; q++) acc[mt][nt][q] = 0.f;

    issue_stage(0, 0);
    if (nch > 1) issue_stage(1, 1); else CP_COMMIT();

    const int a_row_in = lane & 15;
    const int a_chunk  = lane >> 4;
    const int b_row_in = (lane & 7) + ((lane & 16) ? 8 : 0);
    const int b_chunk  = (lane >> 3) & 1;

    for (int i = 0; i < nch; i++) {
        CP_WAIT1();
        __syncthreads();
        if (i + 2 < nch) issue_stage((i + 2) % 3, i + 2);
        else CP_COMMIT();

        uint32_t sbase = smem + (i % 3) * STAGE;
        uint32_t As = sbase, Bs = sbase + ATILE;

        #pragma unroll
        for (int ks = 0; ks < 4; ks++) {
            uint32_t a[2][4];
            #pragma unroll
            for (int mt = 0; mt < 2; mt++) {
                int row = wm * 32 + mt * 16 + a_row_in;
                int ch  = ks * 2 + a_chunk;
                ldsm_x4(As + swz128((uint32_t)(row * 128 + ch * 16)),
                        a[mt][0], a[mt][1], a[mt][2], a[mt][3]);
            }
            uint32_t b[NT][2];
            #pragma unroll
            for (int np = 0; np < NT/2; np++) {
                int row = wn * WN + np * 16 + b_row_in;
                int ch  = ks * 2 + b_chunk;
                ldsm_x4(Bs + swz128((uint32_t)(row * 128 + ch * 16)),
                        b[np*2][0], b[np*2][1], b[np*2+1][0], b[np*2+1][1]);
            }
            #pragma unroll
            for (int mt = 0; mt < 2; mt++)
                #pragma unroll
                for (int nt = 0; nt < NT; nt++)
                    mma16816(acc[mt][nt], a[mt], b[nt]);
        }
        __syncthreads();
    }
    CP_WAIT0();

    #pragma unroll
    for (int mt = 0; mt < 2; mt++) {
        int r0g = m0 + wm * 32 + mt * 16 + (lane >> 2);
        #pragma unroll
        for (int nt = 0; nt < NT; nt++) {
            int col = n0 + wn * WN + nt * 8 + (lane & 3) * 2;
            if (col >= Nreal) continue;
            float bx = 0.f, by = 0.f;
            if (bias) { bx = bias[col]; by = bias[col + 1]; }
            float2 v0 = make_float2(acc[mt][nt][0] + bx, acc[mt][nt][1] + by);
            float2 v1 = make_float2(acc[mt][nt][2] + bx, acc[mt][nt][3] + by);
            *(float2*)(C + (long long)r0g * Nreal + col) = v0;
            *(float2*)(C + (long long)(r0g + 8) * Nreal + col) = v1;
        }
    }
}

// ---------------------------------------------------------------------------
// LSTM elementwise; also writes fp16 h for the logits GEMM A side
// ---------------------------------------------------------------------------
__global__ void lstm_kernel(const float* __restrict__ b_ih,
                            const float* __restrict__ b_hh,
                            float* __restrict__ h_out,
                            float* __restrict__ c_out) {
    int idx = blockIdx.x * blockDim.x + threadIdx.x;
    if (idx >= B_*E_) return;
    int b = idx >> 10, e = idx & (E_ - 1);
    const float* g = g_gates + (long long)b * G4E_;
    float xi = g[e]        + b_ih[e]        + b_hh[e];
    float xf = g[E_   + e] + b_ih[E_   + e] + b_hh[E_   + e];
    float xg = g[2*E_ + e] + b_ih[2*E_ + e] + b_hh[2*E_ + e];
    float xo = g[3*E_ + e] + b_ih[3*E_ + e] + b_hh[3*E_ + e];
    float ig = 1.f / (1.f + __expf(-xi));
    float fg = 1.f / (1.f + __expf(-xf));
    float gg = tanhf(xg);
    float og = 1.f / (1.f + __expf(-xo));
    float c  = fg * g_ctx[idx] + ig * gg;
    float h  = og * tanhf(c);
    h_out[idx] = h;
    c_out[idx] = c;
    g_h[idx] = __float2half_rn(h);
}

// ---------------------------------------------------------------------------
// Lazily-created side stream + events (created OUTSIDE capture; reused).
// ---------------------------------------------------------------------------
static cudaStream_t s_side = nullptr;
static cudaEvent_t  s_evFork = nullptr, s_evG = nullptr, s_evP = nullptr;

extern "C" void kernel_launch(void* const* d_in, const int* in_sizes, int n_in,
                              void* d_out, int out_size) {
    const void *p_tgt=0, *p_enc=0, *p_h0=0, *p_pad=0, *p_emb=0, *p_wproj=0,
               *p_wih=0, *p_whh=0, *p_bih=0, *p_bhh=0, *p_bproj=0;
    int seen_be = 0, seen_ve = 0, seen_w = 0, seen_b4 = 0;
    for (int i = 0; i < n_in; i++) {
        long long s = in_sizes[i];
        if      (s == 512)                  p_tgt = d_in[i];
        else if (s == (long long)B_*ML_*E_) p_enc = d_in[i];
        else if (s == (long long)B_*E_)     { if (seen_be++ == 0) p_h0 = d_in[i]; }
        else if (s == B_*ML_)               p_pad = d_in[i];
        else if (s == (long long)V_*E_)     { if (seen_ve++ == 0) p_emb = d_in[i]; else p_wproj = d_in[i]; }
        else if (s == (long long)G4E_*E_)   { if (seen_w++  == 0) p_wih = d_in[i]; else p_whh = d_in[i]; }
        else if (s == G4E_)                 { if (seen_b4++ == 0) p_bih = d_in[i]; else p_bhh = d_in[i]; }
        else if (s == V_)                   p_bproj = d_in[i];
    }

    const int*   tgt    = (const int*)p_tgt;
    const float* enc    = (const float*)p_enc;
    const float* h0     = (const float*)p_h0;
    const float* emb    = (const float*)p_emb;
    const float* w_ih   = (const float*)p_wih;
    const float* w_hh   = (const float*)p_whh;
    const float* b_ih   = (const float*)p_bih;
    const float* b_hh   = (const float*)p_bhh;
    const float* w_proj = (const float*)p_wproj;
    const float* b_proj = (const float*)p_bproj;

    float* out    = (float*)d_out;
    float* logits = out;
    float* h_out  = out + (long long)B_ * V_;
    float* c_out  = h_out + (long long)B_ * E_;

    float *gates;
    cudaGetSymbolAddress((void**)&gates, g_gates);
    __half *wp, *wg, *ag, *hh;
    cudaGetSymbolAddress((void**)&wp, g_wp);
    cudaGetSymbolAddress((void**)&wg, g_wg);
    cudaGetSymbolAddress((void**)&ag, g_ag);
    cudaGetSymbolAddress((void**)&hh, g_h);

    const int SMEM128 = 3 * (128*128 + 16384);   // 96 KB
    const int SMEM64  = 3 * (64*128 + 16384);    // 72 KB
    const int SMEMATT = ML_ * E_ * 4;            // 200 KB
    cudaFuncSetAttribute(gemm_fp16_mma<128>, cudaFuncAttributeMaxDynamicSharedMemorySize, SMEM128);
    cudaFuncSetAttribute(gemm_fp16_mma<64>,  cudaFuncAttributeMaxDynamicSharedMemorySize, SMEM64);
    cudaFuncSetAttribute(attn_fused_kernel,  cudaFuncAttributeMaxDynamicSharedMemorySize, SMEMATT);

    if (s_side == nullptr) {
        cudaStreamCreateWithFlags(&s_side, cudaStreamNonBlocking);
        cudaEventCreateWithFlags(&s_evFork, cudaEventDisableTiming);
        cudaEventCreateWithFlags(&s_evG,    cudaEventDisableTiming);
        cudaEventCreateWithFlags(&s_evP,    cudaEventDisableTiming);
    }

    // ---- fork: gather + weight conversion on the side stream ----
    cudaEventRecord(s_evFork, 0);
    cudaStreamWaitEvent(s_side, s_evFork, 0);
    {
        gather_words_kernel<<<(B_*(E_/4) + 255)/256, 256, 0, s_side>>>(tgt, emb);
        long long tg = (long long)G4E_ * (KGATE/8);
        conv_wgate_kernel<<<(unsigned)((tg + 255)/256), 256, 0, s_side>>>(w_ih, w_hh);
        cudaEventRecord(s_evG, s_side);
        long long tot = (long long)NPADV * (E_/8);
        conv_wproj_kernel<<<(unsigned)((tot + 255)/256), 256, 0, s_side>>>(w_proj);
        cudaEventRecord(s_evP, s_side);
    }

    // ---- main stream ----
    detect_pad_kernel<<<1, 1024>>>((const unsigned char*)p_pad);
    attn_fused_kernel<<<B_, 512, SMEMATT>>>(enc, h0, p_pad);

    // join: gates GEMM needs gather + converted [w_ih|w_hh]
    cudaStreamWaitEvent(0, s_evG, 0);
    {
        dim3 grid(B_/64, G4E_/128);
        gemm_fp16_mma<64><<<grid, 256, SMEM64>>>(ag, wg, gates, nullptr, KGATE, G4E_);
    }

    lstm_kernel<<<(B_*E_ + 255)/256, 256>>>(b_ih, b_hh, h_out, c_out);

    // join: logits GEMM needs converted w_proj
    cudaStreamWaitEvent(0, s_evP, 0);
    {
        dim3 grid(B_/128, NPADV/128);
        gemm_fp16_mma<128><<<grid, 256, SMEM128>>>(hh, wp, logits, b_proj, E_, V_);
    }
}

// round 13
// speedup vs baseline: 1.0234x; 1.0234x over previous
#include <cuda_runtime.h>
#include <cuda_fp16.h>
#include <math.h>
#include <stdint.h>

#define B_    512
#define E_    1024
#define ML_   50
#define V_    50000
#define G4E_  (4*E_)
#define NPADV 50048          // V padded to multiple of 128
#define KGATE 2048           // gates K: [words|ctx] vs [w_ih|w_hh]

// ---------------- scratch (__device__ globals; allocation-free rule) --------
__device__ float g_ctx[B_*E_];
__device__ float g_gates[(long long)B_*G4E_];

__device__ __half g_wp[(long long)NPADV*E_];     // w_proj fp16 (rows >= V_ zero)
__device__ __half g_wg[(long long)G4E_*KGATE];   // [w_ih | w_hh] fp16
__device__ __half g_ag[B_*KGATE];                // [words | ctx] fp16 (GEMM A)
__device__ __half g_h[B_*E_];                    // h_new fp16 (GEMM A)

union H8 { __half h[8]; uint4 u; };

// ---------------- PTX helpers (arch-stable, sm_80-era) ----------------------
__device__ __forceinline__ uint32_t smem_u32(const void* p) {
    uint32_t a;
    asm("{ .reg .u64 t; cvta.to.shared.u64 t, %1; cvt.u32.u64 %0, t; }" : "=r"(a) : "l"(p));
    return a;
}
#define CP_ASYNC16(dst, src) \
    asm volatile("cp.async.cg.shared.global [%0], [%1], 16;" :: "r"(dst), "l"(src) : "memory")
#define CP_COMMIT() asm volatile("cp.async.commit_group;" ::: "memory")
#define CP_WAIT1()  asm volatile("cp.async.wait_group 1;" ::: "memory")
#define CP_WAIT0()  asm volatile("cp.async.wait_group 0;" ::: "memory")

__device__ __forceinline__ void ldsm_x4(uint32_t addr, uint32_t& r0, uint32_t& r1,
                                        uint32_t& r2, uint32_t& r3) {
    asm volatile("ldmatrix.sync.aligned.m8n8.x4.shared.b16 {%0,%1,%2,%3}, [%4];"
                 : "=r"(r0), "=r"(r1), "=r"(r2), "=r"(r3) : "r"(addr));
}
__device__ __forceinline__ void mma16816(float* c, const uint32_t* a, const uint32_t* b) {
    asm volatile("mma.sync.aligned.m16n8k16.row.col.f32.f16.f16.f32 "
                 "{%0,%1,%2,%3}, {%4,%5,%6,%7}, {%8,%9}, {%0,%1,%2,%3};"
                 : "+f"(c[0]), "+f"(c[1]), "+f"(c[2]), "+f"(c[3])
                 : "r"(a[0]), "r"(a[1]), "r"(a[2]), "r"(a[3]), "r"(b[0]), "r"(b[1]));
}
__device__ __forceinline__ uint32_t swz128(uint32_t o) { return o ^ ((o >> 3) & 0x70); }

// ---------------------------------------------------------------------------
// Embedding gather -> fp16 A cols [0,1024), 4 elems/thread (SIDE stream)
// ---------------------------------------------------------------------------
__global__ void gather_words_kernel(const int* __restrict__ tgt,
                                    const float* __restrict__ emb) {
    int t = blockIdx.x * blockDim.x + threadIdx.x;
    if (t >= B_*(E_/4)) return;
    int b = t / (E_/4), e4 = t % (E_/4);
    float4 v = *(const float4*)(emb + (long long)tgt[b] * E_ + e4*4);
    __half2 h01 = __floats2half2_rn(v.x, v.y);
    __half2 h23 = __floats2half2_rn(v.z, v.w);
    uint2 u = make_uint2(*(uint32_t*)&h01, *(uint32_t*)&h23);
    *(uint2*)&g_ag[b * KGATE + e4*4] = u;
}

// ---------------------------------------------------------------------------
// Single-read attention v2: 1024 threads, 200 KB smem enc tile, two-phase
// pipelined load (energies on rows 0-24 overlap the load of rows 25-49),
// pad-dtype detection folded in (per-block scan of the full pad array from
// L2 during the load shadow; identical deterministic result in every block).
// ---------------------------------------------------------------------------
__global__ void __launch_bounds__(1024, 1) attn_fused_kernel(
    const float* __restrict__ enc,
    const float* __restrict__ h0,
    const void* __restrict__ pad_raw)
{
    extern __shared__ float s_enc[];            // [ML_ * E_] = 200 KB
    __shared__ float4 sh_h4[E_/4];
    __shared__ float  sh_w[ML_];
    __shared__ int    s_gt1, s_off4;

    int b = blockIdx.x;
    int tid = threadIdx.x;
    const uint32_t s_enc_u = smem_u32(s_enc);
    const float* src = enc + (long long)b * ML_ * E_;

    // phase-A load: rows 0-24 (102400 B = 6400 x 16B ops; 6.25/thread)
    #pragma unroll
    for (int j = 0; j < 7; j++) {
        int op = tid + j * 1024;
        if (op < 6400) CP_ASYNC16(s_enc_u + op * 16, (const void*)(src + op * 4));
    }
    CP_COMMIT();
    // phase-B load: rows 25-49
    #pragma unroll
    for (int j = 0; j < 7; j++) {
        int op = tid + j * 1024;
        if (op < 6400) CP_ASYNC16(s_enc_u + 102400 + op * 16,
                                  (const void*)(src + 25600 + op * 4));
    }
    CP_COMMIT();

    // load-shadow work: h into smem + pad dtype scan (L2-resident, all blocks)
    if (tid == 0) { s_gt1 = 0; s_off4 = 0; }
    if (tid < E_/4) sh_h4[tid] = ((const float4*)(h0 + (long long)b*E_))[tid];
    __syncthreads();
    {
        const unsigned char* p8 = (const unsigned char*)pad_raw;
        int gt1 = 0, off4 = 0;
        for (int i = tid; i < B_*ML_; i += 1024) {
            unsigned char v = p8[i];
            if (v > 1) gt1 = 1;
            if (v != 0 && (i & 3) != 0) off4 = 1;
        }
        if (gt1)  atomicOr(&s_gt1, 1);
        if (off4) atomicOr(&s_off4, 1);
    }

    int w = tid >> 5, lane = tid & 31;

    // energies rows 0-24 (after phase-A lands)
    CP_WAIT1();
    __syncthreads();
    if (w < 25) {
        const float4* row4 = (const float4*)(s_enc + w * E_);
        float s = 0.f;
        #pragma unroll
        for (int j = 0; j < 8; j++) {
            float4 x = row4[lane + j*32];
            float4 h = sh_h4[lane + j*32];
            s += x.x*h.x + x.y*h.y + x.z*h.z + x.w*h.w;
        }
        #pragma unroll
        for (int o = 16; o > 0; o >>= 1) s += __shfl_down_sync(0xffffffffu, s, o);
        if (lane == 0) sh_w[w] = s;
    }

    // energies rows 25-49 (after phase-B lands)
    CP_WAIT0();
    __syncthreads();
    if (w < 25) {
        int l = 25 + w;
        const float4* row4 = (const float4*)(s_enc + l * E_);
        float s = 0.f;
        #pragma unroll
        for (int j = 0; j < 8; j++) {
            float4 x = row4[lane + j*32];
            float4 h = sh_h4[lane + j*32];
            s += x.x*h.x + x.y*h.y + x.z*h.z + x.w*h.w;
        }
        #pragma unroll
        for (int o = 16; o > 0; o >>= 1) s += __shfl_down_sync(0xffffffffu, s, o);
        if (lane == 0) sh_w[l] = s;
    }
    __syncthreads();

    // masked softmax (restricted-set form == softmax->mask->renormalize)
    if (tid == 0) {
        int bm = (s_gt1 == 0 && s_off4 != 0) ? 1 : 0;
        const unsigned char* p8 = (const unsigned char*)pad_raw;
        const unsigned int*  pw = (const unsigned int*)pad_raw;
        float mx = -1e30f;
        for (int l = 0; l < ML_; l++) mx = fmaxf(mx, sh_w[l]);
        float sum = 0.f;
        for (int l = 0; l < ML_; l++) {
            bool masked = bm ? (p8[b*ML_ + l] != 0) : (pw[b*ML_ + l] != 0u);
            float v = masked ? 0.f : __expf(sh_w[l] - mx);
            sh_w[l] = v; sum += v;
        }
        float inv = 1.f / sum;
        for (int l = 0; l < ML_; l++) sh_w[l] *= inv;
    }
    __syncthreads();

    // context from smem: thread -> 1 column
    {
        int col = tid;
        float a0 = 0.f;
        #pragma unroll 10
        for (int l = 0; l < ML_; l++) a0 += sh_w[l] * s_enc[l * E_ + col];
        g_ctx[(long long)b*E_ + col] = a0;
        g_ag[b * KGATE + E_ + col] = __float2half_rn(a0);
    }
}

// ---------------------------------------------------------------------------
// fp32 -> fp16 weight converters (SIDE stream, overlapped)
// ---------------------------------------------------------------------------
__global__ void conv_wproj_kernel(const float* __restrict__ src) {
    long long t = (long long)blockIdx.x * blockDim.x + threadIdx.x;
    const long long total = (long long)NPADV * (E_/8);
    if (t >= total) return;
    int row = (int)(t / (E_/8));
    int k0  = (int)(t % (E_/8)) * 8;
    H8 hi;
    if (row < V_) {
        const float4 a = *(const float4*)(src + (long long)row*E_ + k0);
        const float4 b = *(const float4*)(src + (long long)row*E_ + k0 + 4);
        hi.h[0]=__float2half_rn(a.x); hi.h[1]=__float2half_rn(a.y);
        hi.h[2]=__float2half_rn(a.z); hi.h[3]=__float2half_rn(a.w);
        hi.h[4]=__float2half_rn(b.x); hi.h[5]=__float2half_rn(b.y);
        hi.h[6]=__float2half_rn(b.z); hi.h[7]=__float2half_rn(b.w);
    } else {
        hi.u = make_uint4(0u, 0u, 0u, 0u);
    }
    *(uint4*)&g_wp[(long long)row * E_ + k0] = hi.u;
}

__global__ void conv_wgate_kernel(const float* __restrict__ w_ih,
                                  const float* __restrict__ w_hh) {
    long long t = (long long)blockIdx.x * blockDim.x + threadIdx.x;
    const long long total = (long long)G4E_ * (KGATE/8);
    if (t >= total) return;
    int row = (int)(t / (KGATE/8));
    int k0  = (int)(t % (KGATE/8)) * 8;
    const float* s = (k0 < E_) ? (w_ih + (long long)row*E_ + k0)
                               : (w_hh + (long long)row*E_ + (k0 - E_));
    const float4 a = *(const float4*)s;
    const float4 b = *(const float4*)(s + 4);
    H8 hi;
    hi.h[0]=__float2half_rn(a.x); hi.h[1]=__float2half_rn(a.y);
    hi.h[2]=__float2half_rn(a.z); hi.h[3]=__float2half_rn(a.w);
    hi.h[4]=__float2half_rn(b.x); hi.h[5]=__float2half_rn(b.y);
    hi.h[6]=__float2half_rn(b.z); hi.h[7]=__float2half_rn(b.w);
    *(uint4*)&g_wg[(long long)row * KGATE + k0] = hi.u;
}

// ---------------------------------------------------------------------------
// fp16 GEMM via mma.sync (proven): C[M,N] = A[M,K2] * B[N,K2]^T (+bias)
// CTA BMx128, K-chunk 64, 3-stage cp.async pipeline, SW128 smem, ldmatrix.
// ---------------------------------------------------------------------------
template<int BM>
__global__ void __launch_bounds__(256, 2) gemm_fp16_mma(
    const __half* __restrict__ A2, const __half* __restrict__ B2,
    float* __restrict__ C, const float* __restrict__ bias,
    int K2, int Nreal)
{
    constexpr int WMW = (BM == 128) ? 4 : 2;
    constexpr int WNW = 8 / WMW;
    constexpr int WN  = 128 / WNW;
    constexpr int NT  = WN / 8;
    constexpr int ATILE = BM * 128;
    constexpr int STAGE = ATILE + 16384;
    constexpr int OPS = (BM + 128) / 32;
    constexpr int OPSA = BM * 8;

    extern __shared__ char smem_raw[];
    const uint32_t smem = smem_u32(smem_raw);

    const int tid = threadIdx.x;
    const int wid = tid >> 5, lane = tid & 31;
    const int wm = wid % WMW, wn = wid / WMW;
    const int m0 = blockIdx.x * BM, n0 = blockIdx.y * 128;
    const int nch = K2 >> 6;

    const __half* Abase = A2 + (long long)m0 * K2;
    const __half* Bbase = B2 + (long long)n0 * K2;

    auto issue_stage = [&](int stage, int chunk) {
        int kc = chunk * 64;
        uint32_t sbase = smem + stage * STAGE;
        #pragma unroll
        for (int j = 0; j < OPS; j++) {
            int op = tid + j * 256;
            const __half* src;
            uint32_t dst;
            if (op < OPSA) {
                int row = op >> 3, c = op & 7;
                src = Abase + (long long)row * K2 + kc + c * 8;
                dst = sbase + swz128((uint32_t)(row * 128 + c * 16));
            } else {
                int op2 = op - OPSA;
                int row = op2 >> 3, c = op2 & 7;
                src = Bbase + (long long)row * K2 + kc + c * 8;
                dst = sbase + ATILE + swz128((uint32_t)(row * 128 + c * 16));
            }
            CP_ASYNC16(dst, (const void*)src);
        }
        CP_COMMIT();
    };

    float acc[2][NT][4];
    #pragma unroll
    for (int mt = 0; mt < 2; mt++)
        #pragma unroll
        for (int nt = 0; nt < NT; nt++)
            #pragma unroll
            for (int q = 0; q < 4; q++) acc[mt][nt][q] = 0.f;

    issue_stage(0, 0);
    if (nch > 1) issue_stage(1, 1); else CP_COMMIT();

    const int a_row_in = lane & 15;
    const int a_chunk  = lane >> 4;
    const int b_row_in = (lane & 7) + ((lane & 16) ? 8 : 0);
    const int b_chunk  = (lane >> 3) & 1;

    for (int i = 0; i < nch; i++) {
        CP_WAIT1();
        __syncthreads();
        if (i + 2 < nch) issue_stage((i + 2) % 3, i + 2);
        else CP_COMMIT();

        uint32_t sbase = smem + (i % 3) * STAGE;
        uint32_t As = sbase, Bs = sbase + ATILE;

        #pragma unroll
        for (int ks = 0; ks < 4; ks++) {
            uint32_t a[2][4];
            #pragma unroll
            for (int mt = 0; mt < 2; mt++) {
                int row = wm * 32 + mt * 16 + a_row_in;
                int ch  = ks * 2 + a_chunk;
                ldsm_x4(As + swz128((uint32_t)(row * 128 + ch * 16)),
                        a[mt][0], a[mt][1], a[mt][2], a[mt][3]);
            }
            uint32_t b[NT][2];
            #pragma unroll
            for (int np = 0; np < NT/2; np++) {
                int row = wn * WN + np * 16 + b_row_in;
                int ch  = ks * 2 + b_chunk;
                ldsm_x4(Bs + swz128((uint32_t)(row * 128 + ch * 16)),
                        b[np*2][0], b[np*2][1], b[np*2+1][0], b[np*2+1][1]);
            }
            #pragma unroll
            for (int mt = 0; mt < 2; mt++)
                #pragma unroll
                for (int nt = 0; nt < NT; nt++)
                    mma16816(acc[mt][nt], a[mt], b[nt]);
        }
        __syncthreads();
    }
    CP_WAIT0();

    #pragma unroll
    for (int mt = 0; mt < 2; mt++) {
        int r0g = m0 + wm * 32 + mt * 16 + (lane >> 2);
        #pragma unroll
        for (int nt = 0; nt < NT; nt++) {
            int col = n0 + wn * WN + nt * 8 + (lane & 3) * 2;
            if (col >= Nreal) continue;
            float bx = 0.f, by = 0.f;
            if (bias) { bx = bias[col]; by = bias[col + 1]; }
            float2 v0 = make_float2(acc[mt][nt][0] + bx, acc[mt][nt][1] + by);
            float2 v1 = make_float2(acc[mt][nt][2] + bx, acc[mt][nt][3] + by);
            *(float2*)(C + (long long)r0g * Nreal + col) = v0;
            *(float2*)(C + (long long)(r0g + 8) * Nreal + col) = v1;
        }
    }
}

// ---------------------------------------------------------------------------
// LSTM elementwise; also writes fp16 h for the logits GEMM A side
// ---------------------------------------------------------------------------
__global__ void lstm_kernel(const float* __restrict__ b_ih,
                            const float* __restrict__ b_hh,
                            float* __restrict__ h_out,
                            float* __restrict__ c_out) {
    int idx = blockIdx.x * blockDim.x + threadIdx.x;
    if (idx >= B_*E_) return;
    int b = idx >> 10, e = idx & (E_ - 1);
    const float* g = g_gates + (long long)b * G4E_;
    float xi = g[e]        + b_ih[e]        + b_hh[e];
    float xf = g[E_   + e] + b_ih[E_   + e] + b_hh[E_   + e];
    float xg = g[2*E_ + e] + b_ih[2*E_ + e] + b_hh[2*E_ + e];
    float xo = g[3*E_ + e] + b_ih[3*E_ + e] + b_hh[3*E_ + e];
    float ig = 1.f / (1.f + __expf(-xi));
    float fg = 1.f / (1.f + __expf(-xf));
    float gg = tanhf(xg);
    float og = 1.f / (1.f + __expf(-xo));
    float c  = fg * g_ctx[idx] + ig * gg;
    float h  = og * tanhf(c);
    h_out[idx] = h;
    c_out[idx] = c;
    g_h[idx] = __float2half_rn(h);
}

// ---------------------------------------------------------------------------
// Lazily-created side stream + events (created OUTSIDE capture; reused).
// ---------------------------------------------------------------------------
static cudaStream_t s_side = nullptr;
static cudaEvent_t  s_evFork = nullptr, s_evG = nullptr, s_evP = nullptr;

extern "C" void kernel_launch(void* const* d_in, const int* in_sizes, int n_in,
                              void* d_out, int out_size) {
    const void *p_tgt=0, *p_enc=0, *p_h0=0, *p_pad=0, *p_emb=0, *p_wproj=0,
               *p_wih=0, *p_whh=0, *p_bih=0, *p_bhh=0, *p_bproj=0;
    int seen_be = 0, seen_ve = 0, seen_w = 0, seen_b4 = 0;
    for (int i = 0; i < n_in; i++) {
        long long s = in_sizes[i];
        if      (s == 512)                  p_tgt = d_in[i];
        else if (s == (long long)B_*ML_*E_) p_enc = d_in[i];
        else if (s == (long long)B_*E_)     { if (seen_be++ == 0) p_h0 = d_in[i]; }
        else if (s == B_*ML_)               p_pad = d_in[i];
        else if (s == (long long)V_*E_)     { if (seen_ve++ == 0) p_emb = d_in[i]; else p_wproj = d_in[i]; }
        else if (s == (long long)G4E_*E_)   { if (seen_w++  == 0) p_wih = d_in[i]; else p_whh = d_in[i]; }
        else if (s == G4E_)                 { if (seen_b4++ == 0) p_bih = d_in[i]; else p_bhh = d_in[i]; }
        else if (s == V_)                   p_bproj = d_in[i];
    }

    const int*   tgt    = (const int*)p_tgt;
    const float* enc    = (const float*)p_enc;
    const float* h0     = (const float*)p_h0;
    const float* emb    = (const float*)p_emb;
    const float* w_ih   = (const float*)p_wih;
    const float* w_hh   = (const float*)p_whh;
    const float* b_ih   = (const float*)p_bih;
    const float* b_hh   = (const float*)p_bhh;
    const float* w_proj = (const float*)p_wproj;
    const float* b_proj = (const float*)p_bproj;

    float* out    = (float*)d_out;
    float* logits = out;
    float* h_out  = out + (long long)B_ * V_;
    float* c_out  = h_out + (long long)B_ * E_;

    float *gates;
    cudaGetSymbolAddress((void**)&gates, g_gates);
    __half *wp, *wg, *ag, *hh;
    cudaGetSymbolAddress((void**)&wp, g_wp);
    cudaGetSymbolAddress((void**)&wg, g_wg);
    cudaGetSymbolAddress((void**)&ag, g_ag);
    cudaGetSymbolAddress((void**)&hh, g_h);

    const int SMEM128 = 3 * (128*128 + 16384);   // 96 KB
    const int SMEM64  = 3 * (64*128 + 16384);    // 72 KB
    const int SMEMATT = ML_ * E_ * 4;            // 200 KB
    cudaFuncSetAttribute(gemm_fp16_mma<128>, cudaFuncAttributeMaxDynamicSharedMemorySize, SMEM128);
    cudaFuncSetAttribute(gemm_fp16_mma<64>,  cudaFuncAttributeMaxDynamicSharedMemorySize, SMEM64);
    cudaFuncSetAttribute(attn_fused_kernel,  cudaFuncAttributeMaxDynamicSharedMemorySize, SMEMATT);

    if (s_side == nullptr) {
        cudaStreamCreateWithFlags(&s_side, cudaStreamNonBlocking);
        cudaEventCreateWithFlags(&s_evFork, cudaEventDisableTiming);
        cudaEventCreateWithFlags(&s_evG,    cudaEventDisableTiming);
        cudaEventCreateWithFlags(&s_evP,    cudaEventDisableTiming);
    }

    // ---- fork: gather + weight conversion on the side stream ----
    cudaEventRecord(s_evFork, 0);
    cudaStreamWaitEvent(s_side, s_evFork, 0);
    {
        gather_words_kernel<<<(B_*(E_/4) + 255)/256, 256, 0, s_side>>>(tgt, emb);
        long long tg = (long long)G4E_ * (KGATE/8);
        conv_wgate_kernel<<<(unsigned)((tg + 255)/256), 256, 0, s_side>>>(w_ih, w_hh);
        cudaEventRecord(s_evG, s_side);
        long long tot = (long long)NPADV * (E_/8);
        conv_wproj_kernel<<<(unsigned)((tot + 255)/256), 256, 0, s_side>>>(w_proj);
        cudaEventRecord(s_evP, s_side);
    }

    // ---- main stream ----
    attn_fused_kernel<<<B_, 1024, SMEMATT>>>(enc, h0, p_pad);

    // join: gates GEMM needs gather + converted [w_ih|w_hh]
    cudaStreamWaitEvent(0, s_evG, 0);
    {
        dim3 grid(B_/64, G4E_/128);
        gemm_fp16_mma<64><<<grid, 256, SMEM64>>>(ag, wg, gates, nullptr, KGATE, G4E_);
    }

    lstm_kernel<<<(B_*E_ + 255)/256, 256>>>(b_ih, b_hh, h_out, c_out);

    // join: logits GEMM needs converted w_proj
    cudaStreamWaitEvent(0, s_evP, 0);
    {
        dim3 grid(B_/128, NPADV/128);
        gemm_fp16_mma<128><<<grid, 256, SMEM128>>>(hh, wp, logits, b_proj, E_, V_);
    }
}

// round 14
// speedup vs baseline: 1.0552x; 1.0311x over previous
#include <cuda_runtime.h>
#include <cuda_fp16.h>
#include <math.h>
#include <stdint.h>

#define B_    512
#define E_    1024
#define ML_   50
#define V_    50000
#define G4E_  (4*E_)
#define NPADV 50048          // V padded to multiple of 128
#define KGATE 2048           // gates K: [words|ctx] vs [w_ih|w_hh]

// ---------------- scratch (__device__ globals; allocation-free rule) --------
__device__ float g_ctx[B_*E_];
__device__ float g_gates[(long long)B_*G4E_];

__device__ __half g_wp[(long long)NPADV*E_];     // w_proj fp16 (rows >= V_ zero)
__device__ __half g_wg[(long long)G4E_*KGATE];   // [w_ih | w_hh] fp16
__device__ __half g_ag[B_*KGATE];                // [words | ctx] fp16 (GEMM A)
__device__ __half g_h[B_*E_];                    // h_new fp16 (GEMM A)

union H8 { __half h[8]; uint4 u; };

// ---------------- PTX helpers (arch-stable, sm_80-era) ----------------------
__device__ __forceinline__ uint32_t smem_u32(const void* p) {
    uint32_t a;
    asm("{ .reg .u64 t; cvta.to.shared.u64 t, %1; cvt.u32.u64 %0, t; }" : "=r"(a) : "l"(p));
    return a;
}
#define CP_ASYNC16(dst, src) \
    asm volatile("cp.async.cg.shared.global [%0], [%1], 16;" :: "r"(dst), "l"(src) : "memory")
#define CP_COMMIT() asm volatile("cp.async.commit_group;" ::: "memory")
#define CP_WAIT1()  asm volatile("cp.async.wait_group 1;" ::: "memory")
#define CP_WAIT0()  asm volatile("cp.async.wait_group 0;" ::: "memory")

__device__ __forceinline__ void ldsm_x4(uint32_t addr, uint32_t& r0, uint32_t& r1,
                                        uint32_t& r2, uint32_t& r3) {
    asm volatile("ldmatrix.sync.aligned.m8n8.x4.shared.b16 {%0,%1,%2,%3}, [%4];"
                 : "=r"(r0), "=r"(r1), "=r"(r2), "=r"(r3) : "r"(addr));
}
__device__ __forceinline__ void mma16816(float* c, const uint32_t* a, const uint32_t* b) {
    asm volatile("mma.sync.aligned.m16n8k16.row.col.f32.f16.f16.f32 "
                 "{%0,%1,%2,%3}, {%4,%5,%6,%7}, {%8,%9}, {%0,%1,%2,%3};"
                 : "+f"(c[0]), "+f"(c[1]), "+f"(c[2]), "+f"(c[3])
                 : "r"(a[0]), "r"(a[1]), "r"(a[2]), "r"(a[3]), "r"(b[0]), "r"(b[1]));
}
__device__ __forceinline__ uint32_t swz128(uint32_t o) { return o ^ ((o >> 3) & 0x70); }

// ---------------------------------------------------------------------------
// Embedding gather -> fp16 A cols [0,1024), 4 elems/thread (SIDE stream)
// ---------------------------------------------------------------------------
__global__ void gather_words_kernel(const int* __restrict__ tgt,
                                    const float* __restrict__ emb) {
    int t = blockIdx.x * blockDim.x + threadIdx.x;
    if (t >= B_*(E_/4)) return;
    int b = t / (E_/4), e4 = t % (E_/4);
    float4 v = *(const float4*)(emb + (long long)tgt[b] * E_ + e4*4);
    __half2 h01 = __floats2half2_rn(v.x, v.y);
    __half2 h23 = __floats2half2_rn(v.z, v.w);
    uint2 u = make_uint2(*(uint32_t*)&h01, *(uint32_t*)&h23);
    *(uint2*)&g_ag[b * KGATE + e4*4] = u;
}

// ---------------------------------------------------------------------------
// Attention (R11-proven two-pass, 256 threads) + inline pad-dtype detection.
// Context pass re-reads this block's enc tile from L2 (resident).
// ---------------------------------------------------------------------------
__global__ void __launch_bounds__(256, 2) attn_kernel(
    const float* __restrict__ enc,
    const float* __restrict__ h0,
    const void* __restrict__ pad_raw)
{
    int b = blockIdx.x;
    __shared__ float4 sh_h4[E_/4];
    __shared__ float  sh_w[ML_];
    __shared__ int    s_gt1, s_off4;
    int tid = threadIdx.x;

    if (tid == 0) { s_gt1 = 0; s_off4 = 0; }
    const float4* h04 = (const float4*)(h0 + (long long)b*E_);
    if (tid < 256) sh_h4[tid] = h04[tid];
    __syncthreads();

    // pad dtype scan (25.6 KB, L2-resident after first block touches it)
    {
        const unsigned char* p8 = (const unsigned char*)pad_raw;
        int gt1 = 0, off4 = 0;
        for (int i = tid; i < B_*ML_; i += 256) {
            unsigned char v = p8[i];
            if (v > 1) gt1 = 1;
            if (v != 0 && (i & 3) != 0) off4 = 1;
        }
        if (gt1)  atomicOr(&s_gt1, 1);
        if (off4) atomicOr(&s_off4, 1);
    }

    // energies
    int w = tid >> 5, lane = tid & 31;
    for (int l = w; l < ML_; l += 8) {
        const float4* row4 = (const float4*)(enc + ((long long)b*ML_ + l) * E_);
        float s = 0.f;
        #pragma unroll
        for (int j = 0; j < 8; j++) {
            float4 x = row4[lane + j*32];
            float4 h = sh_h4[lane + j*32];
            s += x.x*h.x + x.y*h.y + x.z*h.z + x.w*h.w;
        }
        #pragma unroll
        for (int o = 16; o > 0; o >>= 1) s += __shfl_down_sync(0xffffffffu, s, o);
        if (lane == 0) sh_w[l] = s;
    }
    __syncthreads();

    // masked softmax (restricted-set form)
    if (tid == 0) {
        int bm = (s_gt1 == 0 && s_off4 != 0) ? 1 : 0;
        const unsigned char* p8 = (const unsigned char*)pad_raw;
        const unsigned int*  pw = (const unsigned int*)pad_raw;
        float mx = -1e30f;
        for (int l = 0; l < ML_; l++) mx = fmaxf(mx, sh_w[l]);
        float sum = 0.f;
        for (int l = 0; l < ML_; l++) {
            bool masked = bm ? (p8[b*ML_ + l] != 0) : (pw[b*ML_ + l] != 0u);
            float v = masked ? 0.f : __expf(sh_w[l] - mx);
            sh_w[l] = v; sum += v;
        }
        float inv = 1.f / sum;
        for (int l = 0; l < ML_; l++) sh_w[l] *= inv;
    }
    __syncthreads();

    // context (tile is L2-hot from the energy pass)
    if (tid < 256) {
        const float4* base = (const float4*)enc + (long long)b*ML_*(E_/4) + tid;
        float4 acc = make_float4(0.f, 0.f, 0.f, 0.f);
        #pragma unroll 10
        for (int l = 0; l < ML_; l++) {
            float wl = sh_w[l];
            float4 v = base[l * (E_/4)];
            acc.x += wl*v.x; acc.y += wl*v.y; acc.z += wl*v.z; acc.w += wl*v.w;
        }
        *(float4*)(g_ctx + (long long)b*E_ + tid*4) = acc;
        __half2 h01 = __floats2half2_rn(acc.x, acc.y);
        __half2 h23 = __floats2half2_rn(acc.z, acc.w);
        uint2 u = make_uint2(*(uint32_t*)&h01, *(uint32_t*)&h23);
        *(uint2*)&g_ag[b * KGATE + E_ + tid*4] = u;
    }
}

// ---------------------------------------------------------------------------
// fp32 -> fp16 weight converters (SIDE stream, overlapped)
// ---------------------------------------------------------------------------
__global__ void conv_wproj_kernel(const float* __restrict__ src) {
    long long t = (long long)blockIdx.x * blockDim.x + threadIdx.x;
    const long long total = (long long)NPADV * (E_/8);
    if (t >= total) return;
    int row = (int)(t / (E_/8));
    int k0  = (int)(t % (E_/8)) * 8;
    H8 hi;
    if (row < V_) {
        const float4 a = *(const float4*)(src + (long long)row*E_ + k0);
        const float4 b = *(const float4*)(src + (long long)row*E_ + k0 + 4);
        hi.h[0]=__float2half_rn(a.x); hi.h[1]=__float2half_rn(a.y);
        hi.h[2]=__float2half_rn(a.z); hi.h[3]=__float2half_rn(a.w);
        hi.h[4]=__float2half_rn(b.x); hi.h[5]=__float2half_rn(b.y);
        hi.h[6]=__float2half_rn(b.z); hi.h[7]=__float2half_rn(b.w);
    } else {
        hi.u = make_uint4(0u, 0u, 0u, 0u);
    }
    *(uint4*)&g_wp[(long long)row * E_ + k0] = hi.u;
}

__global__ void conv_wgate_kernel(const float* __restrict__ w_ih,
                                  const float* __restrict__ w_hh) {
    long long t = (long long)blockIdx.x * blockDim.x + threadIdx.x;
    const long long total = (long long)G4E_ * (KGATE/8);
    if (t >= total) return;
    int row = (int)(t / (KGATE/8));
    int k0  = (int)(t % (KGATE/8)) * 8;
    const float* s = (k0 < E_) ? (w_ih + (long long)row*E_ + k0)
                               : (w_hh + (long long)row*E_ + (k0 - E_));
    const float4 a = *(const float4*)s;
    const float4 b = *(const float4*)(s + 4);
    H8 hi;
    hi.h[0]=__float2half_rn(a.x); hi.h[1]=__float2half_rn(a.y);
    hi.h[2]=__float2half_rn(a.z); hi.h[3]=__float2half_rn(a.w);
    hi.h[4]=__float2half_rn(b.x); hi.h[5]=__float2half_rn(b.y);
    hi.h[6]=__float2half_rn(b.z); hi.h[7]=__float2half_rn(b.w);
    *(uint4*)&g_wg[(long long)row * KGATE + k0] = hi.u;
}

// ---------------------------------------------------------------------------
// fp16 GEMM via mma.sync: C[M,N] (+)= A[M,K2](lda) * B[N,K2](ldb)^T (+bias)
// CTA BMx128, K-chunk 64, 3-stage cp.async pipeline, SW128 smem, ldmatrix.
// ---------------------------------------------------------------------------
template<int BM>
__global__ void __launch_bounds__(256, 2) gemm_fp16_mma(
    const __half* __restrict__ A2, int lda,
    const __half* __restrict__ B2, int ldb,
    float* __restrict__ C, const float* __restrict__ bias,
    int K2, int Nreal, int accum)
{
    constexpr int WMW = (BM == 128) ? 4 : 2;
    constexpr int WNW = 8 / WMW;
    constexpr int WN  = 128 / WNW;
    constexpr int NT  = WN / 8;
    constexpr int ATILE = BM * 128;
    constexpr int STAGE = ATILE + 16384;
    constexpr int OPS = (BM + 128) / 32;
    constexpr int OPSA = BM * 8;

    extern __shared__ char smem_raw[];
    const uint32_t smem = smem_u32(smem_raw);

    const int tid = threadIdx.x;
    const int wid = tid >> 5, lane = tid & 31;
    const int wm = wid % WMW, wn = wid / WMW;
    const int m0 = blockIdx.x * BM, n0 = blockIdx.y * 128;
    const int nch = K2 >> 6;

    const __half* Abase = A2 + (long long)m0 * lda;
    const __half* Bbase = B2 + (long long)n0 * ldb;

    auto issue_stage = [&](int stage, int chunk) {
        int kc = chunk * 64;
        uint32_t sbase = smem + stage * STAGE;
        #pragma unroll
        for (int j = 0; j < OPS; j++) {
            int op = tid + j * 256;
            const __half* src;
            uint32_t dst;
            if (op < OPSA) {
                int row = op >> 3, c = op & 7;
                src = Abase + (long long)row * lda + kc + c * 8;
                dst = sbase + swz128((uint32_t)(row * 128 + c * 16));
            } else {
                int op2 = op - OPSA;
                int row = op2 >> 3, c = op2 & 7;
                src = Bbase + (long long)row * ldb + kc + c * 8;
                dst = sbase + ATILE + swz128((uint32_t)(row * 128 + c * 16));
            }
            CP_ASYNC16(dst, (const void*)src);
        }
        CP_COMMIT();
    };

    float acc[2][NT][4];
    #pragma unroll
    for (int mt = 0; mt < 2; mt++)
        #pragma unroll
        for (int nt = 0; nt < NT; nt++)
            #pragma unroll
            for (int q = 0; q < 4; q++) acc[mt][nt][q] = 0.f;

    issue_stage(0, 0);
    if (nch > 1) issue_stage(1, 1); else CP_COMMIT();

    const int a_row_in = lane & 15;
    const int a_chunk  = lane >> 4;
    const int b_row_in = (lane & 7) + ((lane & 16) ? 8 : 0);
    const int b_chunk  = (lane >> 3) & 1;

    for (int i = 0; i < nch; i++) {
        CP_WAIT1();
        __syncthreads();
        if (i + 2 < nch) issue_stage((i + 2) % 3, i + 2);
        else CP_COMMIT();

        uint32_t sbase = smem + (i % 3) * STAGE;
        uint32_t As = sbase, Bs = sbase + ATILE;

        #pragma unroll
        for (int ks = 0; ks < 4; ks++) {
            uint32_t a[2][4];
            #pragma unroll
            for (int mt = 0; mt < 2; mt++) {
                int row = wm * 32 + mt * 16 + a_row_in;
                int ch  = ks * 2 + a_chunk;
                ldsm_x4(As + swz128((uint32_t)(row * 128 + ch * 16)),
                        a[mt][0], a[mt][1], a[mt][2], a[mt][3]);
            }
            uint32_t b[NT][2];
            #pragma unroll
            for (int np = 0; np < NT/2; np++) {
                int row = wn * WN + np * 16 + b_row_in;
                int ch  = ks * 2 + b_chunk;
                ldsm_x4(Bs + swz128((uint32_t)(row * 128 + ch * 16)),
                        b[np*2][0], b[np*2][1], b[np*2+1][0], b[np*2+1][1]);
            }
            #pragma unroll
            for (int mt = 0; mt < 2; mt++)
                #pragma unroll
                for (int nt = 0; nt < NT; nt++)
                    mma16816(acc[mt][nt], a[mt], b[nt]);
        }
        __syncthreads();
    }
    CP_WAIT0();

    #pragma unroll
    for (int mt = 0; mt < 2; mt++) {
        int r0g = m0 + wm * 32 + mt * 16 + (lane >> 2);
        #pragma unroll
        for (int nt = 0; nt < NT; nt++) {
            int col = n0 + wn * WN + nt * 8 + (lane & 3) * 2;
            if (col >= Nreal) continue;
            float bx = 0.f, by = 0.f;
            if (bias) { bx = bias[col]; by = bias[col + 1]; }
            float* p0 = C + (long long)r0g * Nreal + col;
            float* p1 = C + (long long)(r0g + 8) * Nreal + col;
            float2 v0 = make_float2(acc[mt][nt][0] + bx, acc[mt][nt][1] + by);
            float2 v1 = make_float2(acc[mt][nt][2] + bx, acc[mt][nt][3] + by);
            if (accum) {
                float2 o0 = *(float2*)p0, o1 = *(float2*)p1;
                v0.x += o0.x; v0.y += o0.y; v1.x += o1.x; v1.y += o1.y;
            }
            *(float2*)p0 = v0;
            *(float2*)p1 = v1;
        }
    }
}

// ---------------------------------------------------------------------------
// LSTM elementwise; also writes fp16 h for the logits GEMM A side
// ---------------------------------------------------------------------------
__global__ void lstm_kernel(const float* __restrict__ b_ih,
                            const float* __restrict__ b_hh,
                            float* __restrict__ h_out,
                            float* __restrict__ c_out) {
    int idx = blockIdx.x * blockDim.x + threadIdx.x;
    if (idx >= B_*E_) return;
    int b = idx >> 10, e = idx & (E_ - 1);
    const float* g = g_gates + (long long)b * G4E_;
    float xi = g[e]        + b_ih[e]        + b_hh[e];
    float xf = g[E_   + e] + b_ih[E_   + e] + b_hh[E_   + e];
    float xg = g[2*E_ + e] + b_ih[2*E_ + e] + b_hh[2*E_ + e];
    float xo = g[3*E_ + e] + b_ih[3*E_ + e] + b_hh[3*E_ + e];
    float ig = 1.f / (1.f + __expf(-xi));
    float fg = 1.f / (1.f + __expf(-xf));
    float gg = tanhf(xg);
    float og = 1.f / (1.f + __expf(-xo));
    float c  = fg * g_ctx[idx] + ig * gg;
    float h  = og * tanhf(c);
    h_out[idx] = h;
    c_out[idx] = c;
    g_h[idx] = __float2half_rn(h);
}

// ---------------------------------------------------------------------------
// Lazily-created side stream + events (created OUTSIDE capture; reused).
// ---------------------------------------------------------------------------
static cudaStream_t s_side = nullptr;
static cudaEvent_t  s_evFork = nullptr, s_evG = nullptr, s_evP = nullptr;

extern "C" void kernel_launch(void* const* d_in, const int* in_sizes, int n_in,
                              void* d_out, int out_size) {
    const void *p_tgt=0, *p_enc=0, *p_h0=0, *p_pad=0, *p_emb=0, *p_wproj=0,
               *p_wih=0, *p_whh=0, *p_bih=0, *p_bhh=0, *p_bproj=0;
    int seen_be = 0, seen_ve = 0, seen_w = 0, seen_b4 = 0;
    for (int i = 0; i < n_in; i++) {
        long long s = in_sizes[i];
        if      (s == 512)                  p_tgt = d_in[i];
        else if (s == (long long)B_*ML_*E_) p_enc = d_in[i];
        else if (s == (long long)B_*E_)     { if (seen_be++ == 0) p_h0 = d_in[i]; }
        else if (s == B_*ML_)               p_pad = d_in[i];
        else if (s == (long long)V_*E_)     { if (seen_ve++ == 0) p_emb = d_in[i]; else p_wproj = d_in[i]; }
        else if (s == (long long)G4E_*E_)   { if (seen_w++  == 0) p_wih = d_in[i]; else p_whh = d_in[i]; }
        else if (s == G4E_)                 { if (seen_b4++ == 0) p_bih = d_in[i]; else p_bhh = d_in[i]; }
        else if (s == V_)                   p_bproj = d_in[i];
    }

    const int*   tgt    = (const int*)p_tgt;
    const float* enc    = (const float*)p_enc;
    const float* h0     = (const float*)p_h0;
    const float* emb    = (const float*)p_emb;
    const float* w_ih   = (const float*)p_wih;
    const float* w_hh   = (const float*)p_whh;
    const float* b_ih   = (const float*)p_bih;
    const float* b_hh   = (const float*)p_bhh;
    const float* w_proj = (const float*)p_wproj;
    const float* b_proj = (const float*)p_bproj;

    float* out    = (float*)d_out;
    float* logits = out;
    float* h_out  = out + (long long)B_ * V_;
    float* c_out  = h_out + (long long)B_ * E_;

    float *gates;
    cudaGetSymbolAddress((void**)&gates, g_gates);
    __half *wp, *wg, *ag, *hh;
    cudaGetSymbolAddress((void**)&wp, g_wp);
    cudaGetSymbolAddress((void**)&wg, g_wg);
    cudaGetSymbolAddress((void**)&ag, g_ag);
    cudaGetSymbolAddress((void**)&hh, g_h);

    const int SMEM128 = 3 * (128*128 + 16384);   // 96 KB
    const int SMEM64  = 3 * (64*128 + 16384);    // 72 KB
    cudaFuncSetAttribute(gemm_fp16_mma<128>, cudaFuncAttributeMaxDynamicSharedMemorySize, SMEM128);
    cudaFuncSetAttribute(gemm_fp16_mma<64>,  cudaFuncAttributeMaxDynamicSharedMemorySize, SMEM64);

    if (s_side == nullptr) {
        cudaStreamCreateWithFlags(&s_side, cudaStreamNonBlocking);
        cudaEventCreateWithFlags(&s_evFork, cudaEventDisableTiming);
        cudaEventCreateWithFlags(&s_evG,    cudaEventDisableTiming);
        cudaEventCreateWithFlags(&s_evP,    cudaEventDisableTiming);
    }

    // ---- fork: gather + weight conversion + words-half gates GEMM (side) --
    cudaEventRecord(s_evFork, 0);
    cudaStreamWaitEvent(s_side, s_evFork, 0);
    {
        gather_words_kernel<<<(B_*(E_/4) + 255)/256, 256, 0, s_side>>>(tgt, emb);
        long long tg = (long long)G4E_ * (KGATE/8);
        conv_wgate_kernel<<<(unsigned)((tg + 255)/256), 256, 0, s_side>>>(w_ih, w_hh);
        // words-half: gates = words @ w_ih^T  (K cols [0,1024))
        dim3 gridG(B_/64, G4E_/128);
        gemm_fp16_mma<64><<<gridG, 256, SMEM64, s_side>>>(
            ag, KGATE, wg, KGATE, gates, nullptr, E_, G4E_, 0);
        cudaEventRecord(s_evG, s_side);
        long long tot = (long long)NPADV * (E_/8);
        conv_wproj_kernel<<<(unsigned)((tot + 255)/256), 256, 0, s_side>>>(w_proj);
        cudaEventRecord(s_evP, s_side);
    }

    // ---- main stream ----
    attn_kernel<<<B_, 256>>>(enc, h0, p_pad);

    // ctx-half: gates += ctx @ w_hh^T  (K cols [1024,2048))
    cudaStreamWaitEvent(0, s_evG, 0);
    {
        dim3 gridG(B_/64, G4E_/128);
        gemm_fp16_mma<64><<<gridG, 256, SMEM64>>>(
            ag + E_, KGATE, wg + E_, KGATE, gates, nullptr, E_, G4E_, 1);
    }

    lstm_kernel<<<(B_*E_ + 255)/256, 256>>>(b_ih, b_hh, h_out, c_out);

    // join: logits GEMM needs converted w_proj
    cudaStreamWaitEvent(0, s_evP, 0);
    {
        dim3 gridV(B_/128, NPADV/128);
        gemm_fp16_mma<128><<<gridV, 256, SMEM128>>>(
            hh, E_, wp, E_, logits, b_proj, E_, V_, 0);
    }
}

// round 15
// speedup vs baseline: 1.0604x; 1.0050x over previous
#include <cuda_runtime.h>
#include <cuda_fp16.h>
#include <math.h>
#include <stdint.h>

#define B_    512
#define E_    1024
#define ML_   50
#define V_    50000
#define G4E_  (4*E_)
#define NPADV 50048          // V padded to multiple of 128
#define KGATE 2048           // gates K: [words|ctx] vs [w_ih|w_hh]
#define CONVB 1024           // conv blocks appended to the attention grid

// ---------------- scratch (__device__ globals; allocation-free rule) --------
__device__ float g_ctx[B_*E_];
__device__ float g_gates[(long long)B_*G4E_];

__device__ __half g_wp[(long long)NPADV*E_];     // w_proj fp16 (rows >= V_ zero)
__device__ __half g_wg[(long long)G4E_*KGATE];   // [w_ih | w_hh] fp16
__device__ __half g_ag[B_*KGATE];                // [words | ctx] fp16 (GEMM A)
__device__ __half g_h[B_*E_];                    // h_new fp16 (GEMM A)

union H8 { __half h[8]; uint4 u; };

// ---------------- PTX helpers (arch-stable, sm_80-era) ----------------------
__device__ __forceinline__ uint32_t smem_u32(const void* p) {
    uint32_t a;
    asm("{ .reg .u64 t; cvta.to.shared.u64 t, %1; cvt.u32.u64 %0, t; }" : "=r"(a) : "l"(p));
    return a;
}
#define CP_ASYNC16(dst, src) \
    asm volatile("cp.async.cg.shared.global [%0], [%1], 16;" :: "r"(dst), "l"(src) : "memory")
#define CP_COMMIT() asm volatile("cp.async.commit_group;" ::: "memory")
#define CP_WAIT1()  asm volatile("cp.async.wait_group 1;" ::: "memory")
#define CP_WAIT0()  asm volatile("cp.async.wait_group 0;" ::: "memory")

__device__ __forceinline__ void ldsm_x4(uint32_t addr, uint32_t& r0, uint32_t& r1,
                                        uint32_t& r2, uint32_t& r3) {
    asm volatile("ldmatrix.sync.aligned.m8n8.x4.shared.b16 {%0,%1,%2,%3}, [%4];"
                 : "=r"(r0), "=r"(r1), "=r"(r2), "=r"(r3) : "r"(addr));
}
__device__ __forceinline__ void mma16816(float* c, const uint32_t* a, const uint32_t* b) {
    asm volatile("mma.sync.aligned.m16n8k16.row.col.f32.f16.f16.f32 "
                 "{%0,%1,%2,%3}, {%4,%5,%6,%7}, {%8,%9}, {%0,%1,%2,%3};"
                 : "+f"(c[0]), "+f"(c[1]), "+f"(c[2]), "+f"(c[3])
                 : "r"(a[0]), "r"(a[1]), "r"(a[2]), "r"(a[3]), "r"(b[0]), "r"(b[1]));
}
__device__ __forceinline__ uint32_t swz128(uint32_t o) { return o ^ ((o >> 3) & 0x70); }

// ---------------------------------------------------------------------------
// Embedding gather -> fp16 A cols [0,1024), 4 elems/thread (SIDE stream)
// ---------------------------------------------------------------------------
__global__ void gather_words_kernel(const int* __restrict__ tgt,
                                    const float* __restrict__ emb) {
    int t = blockIdx.x * blockDim.x + threadIdx.x;
    if (t >= B_*(E_/4)) return;
    int b = t / (E_/4), e4 = t % (E_/4);
    float4 v = *(const float4*)(emb + (long long)tgt[b] * E_ + e4*4);
    __half2 h01 = __floats2half2_rn(v.x, v.y);
    __half2 h23 = __floats2half2_rn(v.z, v.w);
    uint2 u = make_uint2(*(uint32_t*)&h01, *(uint32_t*)&h23);
    *(uint2*)&g_ag[b * KGATE + e4*4] = u;
}

// ---------------------------------------------------------------------------
// PRELUDE: heterogeneous grid, one launch.
//   blocks [0, B_)          : attention (two-pass, inline pad-detect)
//   blocks [B_, B_+CONVB)   : w_proj fp32 -> fp16 conversion (grid-stride)
// Both phases are DRAM-bound; a single grid forces the work distributor to
// co-schedule them, overlapping their memory traffic.
// ---------------------------------------------------------------------------
__global__ void __launch_bounds__(256) prelude_kernel(
    const float* __restrict__ enc,
    const float* __restrict__ h0,
    const void* __restrict__ pad_raw,
    const float* __restrict__ wproj)
{
    int tid = threadIdx.x;

    if (blockIdx.x >= B_) {
        // ---------------- w_proj converter ----------------
        const long long total = (long long)NPADV * (E_/8);
        long long start = (long long)(blockIdx.x - B_) * 256 + tid;
        for (long long t = start; t < total; t += (long long)CONVB * 256) {
            int row = (int)(t / (E_/8));
            int k0  = (int)(t % (E_/8)) * 8;
            H8 hi;
            if (row < V_) {
                const float4 a = *(const float4*)(wproj + (long long)row*E_ + k0);
                const float4 b = *(const float4*)(wproj + (long long)row*E_ + k0 + 4);
                hi.h[0]=__float2half_rn(a.x); hi.h[1]=__float2half_rn(a.y);
                hi.h[2]=__float2half_rn(a.z); hi.h[3]=__float2half_rn(a.w);
                hi.h[4]=__float2half_rn(b.x); hi.h[5]=__float2half_rn(b.y);
                hi.h[6]=__float2half_rn(b.z); hi.h[7]=__float2half_rn(b.w);
            } else {
                hi.u = make_uint4(0u, 0u, 0u, 0u);
            }
            *(uint4*)&g_wp[(long long)row * E_ + k0] = hi.u;
        }
        return;
    }

    // ---------------- attention ----------------
    int b = blockIdx.x;
    __shared__ float4 sh_h4[E_/4];
    __shared__ float  sh_w[ML_];
    __shared__ int    s_gt1, s_off4;

    if (tid == 0) { s_gt1 = 0; s_off4 = 0; }
    const float4* h04 = (const float4*)(h0 + (long long)b*E_);
    sh_h4[tid] = h04[tid];
    __syncthreads();

    // pad dtype scan (L2-resident)
    {
        const unsigned char* p8 = (const unsigned char*)pad_raw;
        int gt1 = 0, off4 = 0;
        for (int i = tid; i < B_*ML_; i += 256) {
            unsigned char v = p8[i];
            if (v > 1) gt1 = 1;
            if (v != 0 && (i & 3) != 0) off4 = 1;
        }
        if (gt1)  atomicOr(&s_gt1, 1);
        if (off4) atomicOr(&s_off4, 1);
    }

    // energies
    int w = tid >> 5, lane = tid & 31;
    for (int l = w; l < ML_; l += 8) {
        const float4* row4 = (const float4*)(enc + ((long long)b*ML_ + l) * E_);
        float s = 0.f;
        #pragma unroll
        for (int j = 0; j < 8; j++) {
            float4 x = row4[lane + j*32];
            float4 h = sh_h4[lane + j*32];
            s += x.x*h.x + x.y*h.y + x.z*h.z + x.w*h.w;
        }
        #pragma unroll
        for (int o = 16; o > 0; o >>= 1) s += __shfl_down_sync(0xffffffffu, s, o);
        if (lane == 0) sh_w[l] = s;
    }
    __syncthreads();

    // masked softmax (restricted-set form)
    if (tid == 0) {
        int bm = (s_gt1 == 0 && s_off4 != 0) ? 1 : 0;
        const unsigned char* p8 = (const unsigned char*)pad_raw;
        const unsigned int*  pw = (const unsigned int*)pad_raw;
        float mx = -1e30f;
        for (int l = 0; l < ML_; l++) mx = fmaxf(mx, sh_w[l]);
        float sum = 0.f;
        for (int l = 0; l < ML_; l++) {
            bool masked = bm ? (p8[b*ML_ + l] != 0) : (pw[b*ML_ + l] != 0u);
            float v = masked ? 0.f : __expf(sh_w[l] - mx);
            sh_w[l] = v; sum += v;
        }
        float inv = 1.f / sum;
        for (int l = 0; l < ML_; l++) sh_w[l] *= inv;
    }
    __syncthreads();

    // context (tile L2-hot from the energy pass)
    {
        const float4* base = (const float4*)enc + (long long)b*ML_*(E_/4) + tid;
        float4 acc = make_float4(0.f, 0.f, 0.f, 0.f);
        #pragma unroll 10
        for (int l = 0; l < ML_; l++) {
            float wl = sh_w[l];
            float4 v = base[l * (E_/4)];
            acc.x += wl*v.x; acc.y += wl*v.y; acc.z += wl*v.z; acc.w += wl*v.w;
        }
        *(float4*)(g_ctx + (long long)b*E_ + tid*4) = acc;
        __half2 h01 = __floats2half2_rn(acc.x, acc.y);
        __half2 h23 = __floats2half2_rn(acc.z, acc.w);
        uint2 u = make_uint2(*(uint32_t*)&h01, *(uint32_t*)&h23);
        *(uint2*)&g_ag[b * KGATE + E_ + tid*4] = u;
    }
}

// ---------------------------------------------------------------------------
// [w_ih | w_hh] fp32 -> fp16 (SIDE stream)
// ---------------------------------------------------------------------------
__global__ void conv_wgate_kernel(const float* __restrict__ w_ih,
                                  const float* __restrict__ w_hh) {
    long long t = (long long)blockIdx.x * blockDim.x + threadIdx.x;
    const long long total = (long long)G4E_ * (KGATE/8);
    if (t >= total) return;
    int row = (int)(t / (KGATE/8));
    int k0  = (int)(t % (KGATE/8)) * 8;
    const float* s = (k0 < E_) ? (w_ih + (long long)row*E_ + k0)
                               : (w_hh + (long long)row*E_ + (k0 - E_));
    const float4 a = *(const float4*)s;
    const float4 b = *(const float4*)(s + 4);
    H8 hi;
    hi.h[0]=__float2half_rn(a.x); hi.h[1]=__float2half_rn(a.y);
    hi.h[2]=__float2half_rn(a.z); hi.h[3]=__float2half_rn(a.w);
    hi.h[4]=__float2half_rn(b.x); hi.h[5]=__float2half_rn(b.y);
    hi.h[6]=__float2half_rn(b.z); hi.h[7]=__float2half_rn(b.w);
    *(uint4*)&g_wg[(long long)row * KGATE + k0] = hi.u;
}

// ---------------------------------------------------------------------------
// fp16 GEMM via mma.sync: C[M,N] (+)= A[M,K2](lda) * B[N,K2](ldb)^T (+bias)
// CTA BMx128, K-chunk 64, 3-stage cp.async pipeline, SW128 smem, ldmatrix.
// ---------------------------------------------------------------------------
template<int BM>
__global__ void __launch_bounds__(256, 2) gemm_fp16_mma(
    const __half* __restrict__ A2, int lda,
    const __half* __restrict__ B2, int ldb,
    float* __restrict__ C, const float* __restrict__ bias,
    int K2, int Nreal, int accum)
{
    constexpr int WMW = (BM == 128) ? 4 : 2;
    constexpr int WNW = 8 / WMW;
    constexpr int WN  = 128 / WNW;
    constexpr int NT  = WN / 8;
    constexpr int ATILE = BM * 128;
    constexpr int STAGE = ATILE + 16384;
    constexpr int OPS = (BM + 128) / 32;
    constexpr int OPSA = BM * 8;

    extern __shared__ char smem_raw[];
    const uint32_t smem = smem_u32(smem_raw);

    const int tid = threadIdx.x;
    const int wid = tid >> 5, lane = tid & 31;
    const int wm = wid % WMW, wn = wid / WMW;
    const int m0 = blockIdx.x * BM, n0 = blockIdx.y * 128;
    const int nch = K2 >> 6;

    const __half* Abase = A2 + (long long)m0 * lda;
    const __half* Bbase = B2 + (long long)n0 * ldb;

    auto issue_stage = [&](int stage, int chunk) {
        int kc = chunk * 64;
        uint32_t sbase = smem + stage * STAGE;
        #pragma unroll
        for (int j = 0; j < OPS; j++) {
            int op = tid + j * 256;
            const __half* src;
            uint32_t dst;
            if (op < OPSA) {
                int row = op >> 3, c = op & 7;
                src = Abase + (long long)row * lda + kc + c * 8;
                dst = sbase + swz128((uint32_t)(row * 128 + c * 16));
            } else {
                int op2 = op - OPSA;
                int row = op2 >> 3, c = op2 & 7;
                src = Bbase + (long long)row * ldb + kc + c * 8;
                dst = sbase + ATILE + swz128((uint32_t)(row * 128 + c * 16));
            }
            CP_ASYNC16(dst, (const void*)src);
        }
        CP_COMMIT();
    };

    float acc[2][NT][4];
    #pragma unroll
    for (int mt = 0; mt < 2; mt++)
        #pragma unroll
        for (int nt = 0; nt < NT; nt++)
            #pragma unroll
            for (int q = 0; q < 4; q++) acc[mt][nt][q] = 0.f;

    issue_stage(0, 0);
    if (nch > 1) issue_stage(1, 1); else CP_COMMIT();

    const int a_row_in = lane & 15;
    const int a_chunk  = lane >> 4;
    const int b_row_in = (lane & 7) + ((lane & 16) ? 8 : 0);
    const int b_chunk  = (lane >> 3) & 1;

    for (int i = 0; i < nch; i++) {
        CP_WAIT1();
        __syncthreads();
        if (i + 2 < nch) issue_stage((i + 2) % 3, i + 2);
        else CP_COMMIT();

        uint32_t sbase = smem + (i % 3) * STAGE;
        uint32_t As = sbase, Bs = sbase + ATILE;

        #pragma unroll
        for (int ks = 0; ks < 4; ks++) {
            uint32_t a[2][4];
            #pragma unroll
            for (int mt = 0; mt < 2; mt++) {
                int row = wm * 32 + mt * 16 + a_row_in;
                int ch  = ks * 2 + a_chunk;
                ldsm_x4(As + swz128((uint32_t)(row * 128 + ch * 16)),
                        a[mt][0], a[mt][1], a[mt][2], a[mt][3]);
            }
            uint32_t b[NT][2];
            #pragma unroll
            for (int np = 0; np < NT/2; np++) {
                int row = wn * WN + np * 16 + b_row_in;
                int ch  = ks * 2 + b_chunk;
                ldsm_x4(Bs + swz128((uint32_t)(row * 128 + ch * 16)),
                        b[np*2][0], b[np*2][1], b[np*2+1][0], b[np*2+1][1]);
            }
            #pragma unroll
            for (int mt = 0; mt < 2; mt++)
                #pragma unroll
                for (int nt = 0; nt < NT; nt++)
                    mma16816(acc[mt][nt], a[mt], b[nt]);
        }
        __syncthreads();
    }
    CP_WAIT0();

    #pragma unroll
    for (int mt = 0; mt < 2; mt++) {
        int r0g = m0 + wm * 32 + mt * 16 + (lane >> 2);
        #pragma unroll
        for (int nt = 0; nt < NT; nt++) {
            int col = n0 + wn * WN + nt * 8 + (lane & 3) * 2;
            if (col >= Nreal) continue;
            float bx = 0.f, by = 0.f;
            if (bias) { bx = bias[col]; by = bias[col + 1]; }
            float* p0 = C + (long long)r0g * Nreal + col;
            float* p1 = C + (long long)(r0g + 8) * Nreal + col;
            float2 v0 = make_float2(acc[mt][nt][0] + bx, acc[mt][nt][1] + by);
            float2 v1 = make_float2(acc[mt][nt][2] + bx, acc[mt][nt][3] + by);
            if (accum) {
                float2 o0 = *(float2*)p0, o1 = *(float2*)p1;
                v0.x += o0.x; v0.y += o0.y; v1.x += o1.x; v1.y += o1.y;
            }
            *(float2*)p0 = v0;
            *(float2*)p1 = v1;
        }
    }
}

// ---------------------------------------------------------------------------
// LSTM elementwise; also writes fp16 h for the logits GEMM A side
// ---------------------------------------------------------------------------
__global__ void lstm_kernel(const float* __restrict__ b_ih,
                            const float* __restrict__ b_hh,
                            float* __restrict__ h_out,
                            float* __restrict__ c_out) {
    int idx = blockIdx.x * blockDim.x + threadIdx.x;
    if (idx >= B_*E_) return;
    int b = idx >> 10, e = idx & (E_ - 1);
    const float* g = g_gates + (long long)b * G4E_;
    float xi = g[e]        + b_ih[e]        + b_hh[e];
    float xf = g[E_   + e] + b_ih[E_   + e] + b_hh[E_   + e];
    float xg = g[2*E_ + e] + b_ih[2*E_ + e] + b_hh[2*E_ + e];
    float xo = g[3*E_ + e] + b_ih[3*E_ + e] + b_hh[3*E_ + e];
    float ig = 1.f / (1.f + __expf(-xi));
    float fg = 1.f / (1.f + __expf(-xf));
    float gg = tanhf(xg);
    float og = 1.f / (1.f + __expf(-xo));
    float c  = fg * g_ctx[idx] + ig * gg;
    float h  = og * tanhf(c);
    h_out[idx] = h;
    c_out[idx] = c;
    g_h[idx] = __float2half_rn(h);
}

// ---------------------------------------------------------------------------
// Lazily-created side stream + events (created OUTSIDE capture; reused).
// ---------------------------------------------------------------------------
static cudaStream_t s_side = nullptr;
static cudaEvent_t  s_evFork = nullptr, s_evG = nullptr;

extern "C" void kernel_launch(void* const* d_in, const int* in_sizes, int n_in,
                              void* d_out, int out_size) {
    const void *p_tgt=0, *p_enc=0, *p_h0=0, *p_pad=0, *p_emb=0, *p_wproj=0,
               *p_wih=0, *p_whh=0, *p_bih=0, *p_bhh=0, *p_bproj=0;
    int seen_be = 0, seen_ve = 0, seen_w = 0, seen_b4 = 0;
    for (int i = 0; i < n_in; i++) {
        long long s = in_sizes[i];
        if      (s == 512)                  p_tgt = d_in[i];
        else if (s == (long long)B_*ML_*E_) p_enc = d_in[i];
        else if (s == (long long)B_*E_)     { if (seen_be++ == 0) p_h0 = d_in[i]; }
        else if (s == B_*ML_)               p_pad = d_in[i];
        else if (s == (long long)V_*E_)     { if (seen_ve++ == 0) p_emb = d_in[i]; else p_wproj = d_in[i]; }
        else if (s == (long long)G4E_*E_)   { if (seen_w++  == 0) p_wih = d_in[i]; else p_whh = d_in[i]; }
        else if (s == G4E_)                 { if (seen_b4++ == 0) p_bih = d_in[i]; else p_bhh = d_in[i]; }
        else if (s == V_)                   p_bproj = d_in[i];
    }

    const int*   tgt    = (const int*)p_tgt;
    const float* enc    = (const float*)p_enc;
    const float* h0     = (const float*)p_h0;
    const float* emb    = (const float*)p_emb;
    const float* w_ih   = (const float*)p_wih;
    const float* w_hh   = (const float*)p_whh;
    const float* b_ih   = (const float*)p_bih;
    const float* b_hh   = (const float*)p_bhh;
    const float* w_proj = (const float*)p_wproj;
    const float* b_proj = (const float*)p_bproj;

    float* out    = (float*)d_out;
    float* logits = out;
    float* h_out  = out + (long long)B_ * V_;
    float* c_out  = h_out + (long long)B_ * E_;

    float *gates;
    cudaGetSymbolAddress((void**)&gates, g_gates);
    __half *wp, *wg, *ag, *hh;
    cudaGetSymbolAddress((void**)&wp, g_wp);
    cudaGetSymbolAddress((void**)&wg, g_wg);
    cudaGetSymbolAddress((void**)&ag, g_ag);
    cudaGetSymbolAddress((void**)&hh, g_h);

    const int SMEM128 = 3 * (128*128 + 16384);   // 96 KB
    const int SMEM64  = 3 * (64*128 + 16384);    // 72 KB
    cudaFuncSetAttribute(gemm_fp16_mma<128>, cudaFuncAttributeMaxDynamicSharedMemorySize, SMEM128);
    cudaFuncSetAttribute(gemm_fp16_mma<64>,  cudaFuncAttributeMaxDynamicSharedMemorySize, SMEM64);

    if (s_side == nullptr) {
        cudaStreamCreateWithFlags(&s_side, cudaStreamNonBlocking);
        cudaEventCreateWithFlags(&s_evFork, cudaEventDisableTiming);
        cudaEventCreateWithFlags(&s_evG,    cudaEventDisableTiming);
    }

    // ---- fork: gather + wgate conversion + words-half gates GEMM (side) ----
    cudaEventRecord(s_evFork, 0);
    cudaStreamWaitEvent(s_side, s_evFork, 0);
    {
        gather_words_kernel<<<(B_*(E_/4) + 255)/256, 256, 0, s_side>>>(tgt, emb);
        long long tg = (long long)G4E_ * (KGATE/8);
        conv_wgate_kernel<<<(unsigned)((tg + 255)/256), 256, 0, s_side>>>(w_ih, w_hh);
        // words-half: gates = words @ w_ih^T  (K cols [0,1024))
        dim3 gridG(B_/64, G4E_/128);
        gemm_fp16_mma<64><<<gridG, 256, SMEM64, s_side>>>(
            ag, KGATE, wg, KGATE, gates, nullptr, E_, G4E_, 0);
        cudaEventRecord(s_evG, s_side);
    }

    // ---- main: heterogeneous prelude (attention + w_proj conversion) ----
    prelude_kernel<<<B_ + CONVB, 256>>>(enc, h0, p_pad, w_proj);

    // ctx-half: gates += ctx @ w_hh^T  (K cols [1024,2048))
    cudaStreamWaitEvent(0, s_evG, 0);
    {
        dim3 gridG(B_/64, G4E_/128);
        gemm_fp16_mma<64><<<gridG, 256, SMEM64>>>(
            ag + E_, KGATE, wg + E_, KGATE, gates, nullptr, E_, G4E_, 1);
    }

    lstm_kernel<<<(B_*E_ + 255)/256, 256>>>(b_ih, b_hh, h_out, c_out);

    // logits GEMM (wp produced by the prelude on this same stream)
    {
        dim3 gridV(B_/128, NPADV/128);
        gemm_fp16_mma<128><<<gridV, 256, SMEM128>>>(
            hh, E_, wp, E_, logits, b_proj, E_, V_, 0);
    }
}

// round 16
// speedup vs baseline: 1.0755x; 1.0142x over previous
#include <cuda_runtime.h>
#include <cuda_fp16.h>
#include <math.h>
#include <stdint.h>

#define B_    512
#define E_    1024
#define ML_   50
#define V_    50000
#define G4E_  (4*E_)
#define KGATE 2048           // gates K: [words|ctx] vs [w_ih|w_hh]

#define NB_ATT   B_          // attention blocks
#define NB_WG    256         // wgate-conversion blocks (grid-stride)
#define NB_GATH  64          // gather blocks (grid-stride)
#define NB_TOTAL (NB_ATT + NB_WG + NB_GATH)

// ---------------- scratch (__device__ globals; allocation-free rule) --------
__device__ float g_ctx[B_*E_];
__device__ float g_gates[(long long)B_*G4E_];

__device__ __half g_wg[(long long)G4E_*KGATE];   // [w_ih | w_hh] fp16
__device__ __half g_ag[B_*KGATE];                // [words | ctx] fp16 (GEMM A)
__device__ __half g_h[B_*E_];                    // h_new fp16 (GEMM A)

union H8 { __half h[8]; uint4 u; };

// ---------------- PTX helpers (arch-stable, sm_80-era) ----------------------
__device__ __forceinline__ uint32_t smem_u32(const void* p) {
    uint32_t a;
    asm("{ .reg .u64 t; cvta.to.shared.u64 t, %1; cvt.u32.u64 %0, t; }" : "=r"(a) : "l"(p));
    return a;
}
#define CP_ASYNC16(dst, src) \
    asm volatile("cp.async.cg.shared.global [%0], [%1], 16;" :: "r"(dst), "l"(src) : "memory")
#define CP_COMMIT() asm volatile("cp.async.commit_group;" ::: "memory")
#define CP_WAIT1()  asm volatile("cp.async.wait_group 1;" ::: "memory")
#define CP_WAIT0()  asm volatile("cp.async.wait_group 0;" ::: "memory")

__device__ __forceinline__ void ldsm_x4(uint32_t addr, uint32_t& r0, uint32_t& r1,
                                        uint32_t& r2, uint32_t& r3) {
    asm volatile("ldmatrix.sync.aligned.m8n8.x4.shared.b16 {%0,%1,%2,%3}, [%4];"
                 : "=r"(r0), "=r"(r1), "=r"(r2), "=r"(r3) : "r"(addr));
}
__device__ __forceinline__ void mma16816(float* c, const uint32_t* a, const uint32_t* b) {
    asm volatile("mma.sync.aligned.m16n8k16.row.col.f32.f16.f16.f32 "
                 "{%0,%1,%2,%3}, {%4,%5,%6,%7}, {%8,%9}, {%0,%1,%2,%3};"
                 : "+f"(c[0]), "+f"(c[1]), "+f"(c[2]), "+f"(c[3])
                 : "r"(a[0]), "r"(a[1]), "r"(a[2]), "r"(a[3]), "r"(b[0]), "r"(b[1]));
}
__device__ __forceinline__ uint32_t swz128(uint32_t o) { return o ^ ((o >> 3) & 0x70); }
__device__ __forceinline__ uint32_t swz64 (uint32_t o) { return o ^ ((o >> 3) & 0x30); }

// ---------------------------------------------------------------------------
// PRELUDE: one heterogeneous launch, three block classes.
//   [0, NB_ATT)                : attention (two-pass, inline pad-detect)
//   [NB_ATT, NB_ATT+NB_WG)     : [w_ih|w_hh] fp32->fp16 (grid-stride)
//   [NB_ATT+NB_WG, NB_TOTAL)   : embedding gather -> fp16 (grid-stride)
// ---------------------------------------------------------------------------
__global__ void __launch_bounds__(256) prelude_kernel(
    const float* __restrict__ enc,
    const float* __restrict__ h0,
    const void* __restrict__ pad_raw,
    const float* __restrict__ w_ih,
    const float* __restrict__ w_hh,
    const int*   __restrict__ tgt,
    const float* __restrict__ emb)
{
    int tid = threadIdx.x;

    if (blockIdx.x >= NB_ATT + NB_WG) {
        // ---------------- embedding gather ----------------
        const int total = B_*(E_/4);
        int start = (blockIdx.x - NB_ATT - NB_WG) * 256 + tid;
        for (int t = start; t < total; t += NB_GATH * 256) {
            int b = t / (E_/4), e4 = t % (E_/4);
            float4 v = *(const float4*)(emb + (long long)tgt[b] * E_ + e4*4);
            __half2 h01 = __floats2half2_rn(v.x, v.y);
            __half2 h23 = __floats2half2_rn(v.z, v.w);
            uint2 u = make_uint2(*(uint32_t*)&h01, *(uint32_t*)&h23);
            *(uint2*)&g_ag[b * KGATE + e4*4] = u;
        }
        return;
    }

    if (blockIdx.x >= NB_ATT) {
        // ---------------- wgate converter ----------------
        const long long total = (long long)G4E_ * (KGATE/8);
        long long start = (long long)(blockIdx.x - NB_ATT) * 256 + tid;
        for (long long t = start; t < total; t += (long long)NB_WG * 256) {
            int row = (int)(t / (KGATE/8));
            int k0  = (int)(t % (KGATE/8)) * 8;
            const float* s = (k0 < E_) ? (w_ih + (long long)row*E_ + k0)
                                       : (w_hh + (long long)row*E_ + (k0 - E_));
            const float4 a = *(const float4*)s;
            const float4 b = *(const float4*)(s + 4);
            H8 hi;
            hi.h[0]=__float2half_rn(a.x); hi.h[1]=__float2half_rn(a.y);
            hi.h[2]=__float2half_rn(a.z); hi.h[3]=__float2half_rn(a.w);
            hi.h[4]=__float2half_rn(b.x); hi.h[5]=__float2half_rn(b.y);
            hi.h[6]=__float2half_rn(b.z); hi.h[7]=__float2half_rn(b.w);
            *(uint4*)&g_wg[(long long)row * KGATE + k0] = hi.u;
        }
        return;
    }

    // ---------------- attention ----------------
    int b = blockIdx.x;
    __shared__ float4 sh_h4[E_/4];
    __shared__ float  sh_w[ML_];
    __shared__ int    s_gt1, s_off4;

    if (tid == 0) { s_gt1 = 0; s_off4 = 0; }
    sh_h4[tid] = ((const float4*)(h0 + (long long)b*E_))[tid];
    __syncthreads();

    {
        const unsigned char* p8 = (const unsigned char*)pad_raw;
        int gt1 = 0, off4 = 0;
        for (int i = tid; i < B_*ML_; i += 256) {
            unsigned char v = p8[i];
            if (v > 1) gt1 = 1;
            if (v != 0 && (i & 3) != 0) off4 = 1;
        }
        if (gt1)  atomicOr(&s_gt1, 1);
        if (off4) atomicOr(&s_off4, 1);
    }

    int w = tid >> 5, lane = tid & 31;
    for (int l = w; l < ML_; l += 8) {
        const float4* row4 = (const float4*)(enc + ((long long)b*ML_ + l) * E_);
        float s = 0.f;
        #pragma unroll
        for (int j = 0; j < 8; j++) {
            float4 x = row4[lane + j*32];
            float4 h = sh_h4[lane + j*32];
            s += x.x*h.x + x.y*h.y + x.z*h.z + x.w*h.w;
        }
        #pragma unroll
        for (int o = 16; o > 0; o >>= 1) s += __shfl_down_sync(0xffffffffu, s, o);
        if (lane == 0) sh_w[l] = s;
    }
    __syncthreads();

    if (tid == 0) {
        int bm = (s_gt1 == 0 && s_off4 != 0) ? 1 : 0;
        const unsigned char* p8 = (const unsigned char*)pad_raw;
        const unsigned int*  pw = (const unsigned int*)pad_raw;
        float mx = -1e30f;
        for (int l = 0; l < ML_; l++) mx = fmaxf(mx, sh_w[l]);
        float sum = 0.f;
        for (int l = 0; l < ML_; l++) {
            bool masked = bm ? (p8[b*ML_ + l] != 0) : (pw[b*ML_ + l] != 0u);
            float v = masked ? 0.f : __expf(sh_w[l] - mx);
            sh_w[l] = v; sum += v;
        }
        float inv = 1.f / sum;
        for (int l = 0; l < ML_; l++) sh_w[l] *= inv;
    }
    __syncthreads();

    {
        const float4* base = (const float4*)enc + (long long)b*ML_*(E_/4) + tid;
        float4 acc = make_float4(0.f, 0.f, 0.f, 0.f);
        #pragma unroll 10
        for (int l = 0; l < ML_; l++) {
            float wl = sh_w[l];
            float4 v = base[l * (E_/4)];
            acc.x += wl*v.x; acc.y += wl*v.y; acc.z += wl*v.z; acc.w += wl*v.w;
        }
        *(float4*)(g_ctx + (long long)b*E_ + tid*4) = acc;
        __half2 h01 = __floats2half2_rn(acc.x, acc.y);
        __half2 h23 = __floats2half2_rn(acc.z, acc.w);
        uint2 u = make_uint2(*(uint32_t*)&h01, *(uint32_t*)&h23);
        *(uint2*)&g_ag[b * KGATE + E_ + tid*4] = u;
    }
}

// ---------------------------------------------------------------------------
// fp16 GEMM via mma.sync (proven): C[M,N] = A[M,K2] * B[N,K2]^T
// CTA BMx128, K-chunk 64, 3-stage cp.async pipeline, SW128 smem, ldmatrix.
// ---------------------------------------------------------------------------
template<int BM>
__global__ void __launch_bounds__(256, 2) gemm_fp16_mma(
    const __half* __restrict__ A2, const __half* __restrict__ B2,
    float* __restrict__ C, const float* __restrict__ bias,
    int K2, int Nreal)
{
    constexpr int WMW = (BM == 128) ? 4 : 2;
    constexpr int WNW = 8 / WMW;
    constexpr int WN  = 128 / WNW;
    constexpr int NT  = WN / 8;
    constexpr int ATILE = BM * 128;
    constexpr int STAGE = ATILE + 16384;
    constexpr int OPS = (BM + 128) / 32;
    constexpr int OPSA = BM * 8;

    extern __shared__ char smem_raw[];
    const uint32_t smem = smem_u32(smem_raw);

    const int tid = threadIdx.x;
    const int wid = tid >> 5, lane = tid & 31;
    const int wm = wid % WMW, wn = wid / WMW;
    const int m0 = blockIdx.x * BM, n0 = blockIdx.y * 128;
    const int nch = K2 >> 6;

    const __half* Abase = A2 + (long long)m0 * K2;
    const __half* Bbase = B2 + (long long)n0 * K2;

    auto issue_stage = [&](int stage, int chunk) {
        int kc = chunk * 64;
        uint32_t sbase = smem + stage * STAGE;
        #pragma unroll
        for (int j = 0; j < OPS; j++) {
            int op = tid + j * 256;
            const __half* src;
            uint32_t dst;
            if (op < OPSA) {
                int row = op >> 3, c = op & 7;
                src = Abase + (long long)row * K2 + kc + c * 8;
                dst = sbase + swz128((uint32_t)(row * 128 + c * 16));
            } else {
                int op2 = op - OPSA;
                int row = op2 >> 3, c = op2 & 7;
                src = Bbase + (long long)row * K2 + kc + c * 8;
                dst = sbase + ATILE + swz128((uint32_t)(row * 128 + c * 16));
            }
            CP_ASYNC16(dst, (const void*)src);
        }
        CP_COMMIT();
    };

    float acc[2][NT][4];
    #pragma unroll
    for (int mt = 0; mt < 2; mt++)
        #pragma unroll
        for (int nt = 0; nt < NT; nt++)
            #pragma unroll
            for (int q = 0; q < 4; q++) acc[mt][nt][q] = 0.f;

    issue_stage(0, 0);
    if (nch > 1) issue_stage(1, 1); else CP_COMMIT();

    const int a_row_in = lane & 15;
    const int a_chunk  = lane >> 4;
    const int b_row_in = (lane & 7) + ((lane & 16) ? 8 : 0);
    const int b_chunk  = (lane >> 3) & 1;

    for (int i = 0; i < nch; i++) {
        CP_WAIT1();
        __syncthreads();
        if (i + 2 < nch) issue_stage((i + 2) % 3, i + 2);
        else CP_COMMIT();

        uint32_t sbase = smem + (i % 3) * STAGE;
        uint32_t As = sbase, Bs = sbase + ATILE;

        #pragma unroll
        for (int ks = 0; ks < 4; ks++) {
            uint32_t a[2][4];
            #pragma unroll
            for (int mt = 0; mt < 2; mt++) {
                int row = wm * 32 + mt * 16 + a_row_in;
                int ch  = ks * 2 + a_chunk;
                ldsm_x4(As + swz128((uint32_t)(row * 128 + ch * 16)),
                        a[mt][0], a[mt][1], a[mt][2], a[mt][3]);
            }
            uint32_t b[NT][2];
            #pragma unroll
            for (int np = 0; np < NT/2; np++) {
                int row = wn * WN + np * 16 + b_row_in;
                int ch  = ks * 2 + b_chunk;
                ldsm_x4(Bs + swz128((uint32_t)(row * 128 + ch * 16)),
                        b[np*2][0], b[np*2][1], b[np*2+1][0], b[np*2+1][1]);
            }
            #pragma unroll
            for (int mt = 0; mt < 2; mt++)
                #pragma unroll
                for (int nt = 0; nt < NT; nt++)
                    mma16816(acc[mt][nt], a[mt], b[nt]);
        }
        __syncthreads();
    }
    CP_WAIT0();

    #pragma unroll
    for (int mt = 0; mt < 2; mt++) {
        int r0g = m0 + wm * 32 + mt * 16 + (lane >> 2);
        #pragma unroll
        for (int nt = 0; nt < NT; nt++) {
            int col = n0 + wn * WN + nt * 8 + (lane & 3) * 2;
            if (col >= Nreal) continue;
            float bx = 0.f, by = 0.f;
            if (bias) { bx = bias[col]; by = bias[col + 1]; }
            float2 v0 = make_float2(acc[mt][nt][0] + bx, acc[mt][nt][1] + by);
            float2 v1 = make_float2(acc[mt][nt][2] + bx, acc[mt][nt][3] + by);
            *(float2*)(C + (long long)r0g * Nreal + col) = v0;
            *(float2*)(C + (long long)(r0g + 8) * Nreal + col) = v1;
        }
    }
}

// ---------------------------------------------------------------------------
// GEMM, fp16 A x fp32 B (in-smem convert; R10-proven): C = A*B^T (+bias)
// K-chunk = 32 fp32. Stage: A fp16 (BMx64B) + B fp16 (128x64B) + B fp32
// (128x128B). cp.async streams A(fp16)+B(fp32); convert phase feeds mma.
// ---------------------------------------------------------------------------
template<int BM>
__global__ void __launch_bounds__(256, 2) gemm_f32b(
    const __half* __restrict__ A,
    const float* __restrict__ B0,
    int bstride, int nbrows,
    float* __restrict__ C, const float* __restrict__ bias,
    int K, int Nreal)
{
    constexpr int WMW = (BM == 128) ? 4 : 2;
    constexpr int WNW = 8 / WMW;
    constexpr int WN  = 128 / WNW;
    constexpr int NT  = WN / 8;
    constexpr int AT_B   = BM * 64;
    constexpr int BH_B   = 128 * 64;
    constexpr int BF_B   = 128 * 128;
    constexpr int STAGE  = AT_B + BH_B + BF_B;
    constexpr int AOPS   = BM * 4 / 256;
    extern __shared__ char smem_raw[];
    const uint32_t smem = smem_u32(smem_raw);

    const int tid = threadIdx.x;
    const int wid = tid >> 5, lane = tid & 31;
    const int wm = wid % WMW, wn = wid / WMW;
    const int m0 = blockIdx.x * BM, n0 = blockIdx.y * 128;
    const int nch = K >> 5;

    auto issue_stage = [&](int stage, int chunk) {
        int kc = chunk * 32;
        uint32_t sb = smem + stage * STAGE;
        #pragma unroll
        for (int j = 0; j < AOPS; j++) {
            int op = tid + j * 256;
            int row = op >> 2, c = op & 3;
            const __half* src = A + (long long)(m0 + row) * K + kc + c * 8;
            CP_ASYNC16(sb + swz64((uint32_t)(row * 64 + c * 16)), (const void*)src);
        }
        #pragma unroll
        for (int j = 0; j < 4; j++) {
            int op = tid + j * 256;
            int row = op >> 3, c = op & 7;
            int gn = n0 + row; if (gn >= nbrows) gn = nbrows - 1;
            const float* src = B0 + (long long)gn * bstride + kc + c * 4;
            CP_ASYNC16(sb + AT_B + BH_B + swz128((uint32_t)(row * 128 + c * 16)),
                       (const void*)src);
        }
        CP_COMMIT();
    };

    float acc[2][NT][4];
    #pragma unroll
    for (int mt = 0; mt < 2; mt++)
        #pragma unroll
        for (int nt = 0; nt < NT; nt++)
            #pragma unroll
            for (int q = 0; q < 4; q++) acc[mt][nt][q] = 0.f;

    issue_stage(0, 0);
    if (nch > 1) issue_stage(1, 1); else CP_COMMIT();

    const int a_row_in = lane & 15;
    const int a_chunk  = lane >> 4;
    const int b_row_in = (lane & 7) + ((lane & 16) ? 8 : 0);
    const int b_chunk  = (lane >> 3) & 1;
    const int cr = tid >> 1, chh = tid & 1;

    for (int i = 0; i < nch; i++) {
        CP_WAIT1();
        __syncthreads();

        uint32_t sb = smem + (i % 3) * STAGE;
        uint32_t As = sb, Bs = sb + AT_B, Bf = sb + AT_B + BH_B;

        {
            float4 v0 = *(const float4*)(smem_raw + (Bf - smem) + swz128((uint32_t)(cr*128 + chh*64)));
            float4 v1 = *(const float4*)(smem_raw + (Bf - smem) + swz128((uint32_t)(cr*128 + chh*64 + 16)));
            float4 v2 = *(const float4*)(smem_raw + (Bf - smem) + swz128((uint32_t)(cr*128 + chh*64 + 32)));
            float4 v3 = *(const float4*)(smem_raw + (Bf - smem) + swz128((uint32_t)(cr*128 + chh*64 + 48)));
            __half2 h0 = __floats2half2_rn(v0.x, v0.y), h1 = __floats2half2_rn(v0.z, v0.w);
            __half2 h2 = __floats2half2_rn(v1.x, v1.y), h3 = __floats2half2_rn(v1.z, v1.w);
            __half2 h4 = __floats2half2_rn(v2.x, v2.y), h5 = __floats2half2_rn(v2.z, v2.w);
            __half2 h6 = __floats2half2_rn(v3.x, v3.y), h7 = __floats2half2_rn(v3.z, v3.w);
            uint4 u0 = make_uint4(*(uint32_t*)&h0, *(uint32_t*)&h1, *(uint32_t*)&h2, *(uint32_t*)&h3);
            uint4 u1 = make_uint4(*(uint32_t*)&h4, *(uint32_t*)&h5, *(uint32_t*)&h6, *(uint32_t*)&h7);
            *(uint4*)(smem_raw + (Bs - smem) + swz64((uint32_t)(cr*64 + chh*32)))      = u0;
            *(uint4*)(smem_raw + (Bs - smem) + swz64((uint32_t)(cr*64 + chh*32 + 16))) = u1;
        }
        __syncthreads();

        if (i + 2 < nch) issue_stage((i + 2) % 3, i + 2);
        else CP_COMMIT();

        #pragma unroll
        for (int ks = 0; ks < 2; ks++) {
            uint32_t a[2][4];
            #pragma unroll
            for (int mt = 0; mt < 2; mt++) {
                int row = wm * 32 + mt * 16 + a_row_in;
                int ch  = ks * 2 + a_chunk;
                ldsm_x4(As + swz64((uint32_t)(row * 64 + ch * 16)),
                        a[mt][0], a[mt][1], a[mt][2], a[mt][3]);
            }
            uint32_t b[NT][2];
            #pragma unroll
            for (int np = 0; np < NT/2; np++) {
                int row = wn * WN + np * 16 + b_row_in;
                int ch  = ks * 2 + b_chunk;
                ldsm_x4(Bs + swz64((uint32_t)(row * 64 + ch * 16)),
                        b[np*2][0], b[np*2][1], b[np*2+1][0], b[np*2+1][1]);
            }
            #pragma unroll
            for (int mt = 0; mt < 2; mt++)
                #pragma unroll
                for (int nt = 0; nt < NT; nt++)
                    mma16816(acc[mt][nt], a[mt], b[nt]);
        }
        __syncthreads();
    }
    CP_WAIT0();

    #pragma unroll
    for (int mt = 0; mt < 2; mt++) {
        int r0g = m0 + wm * 32 + mt * 16 + (lane >> 2);
        #pragma unroll
        for (int nt = 0; nt < NT; nt++) {
            int col = n0 + wn * WN + nt * 8 + (lane & 3) * 2;
            if (col >= Nreal) continue;
            float bx = 0.f, by = 0.f;
            if (bias) { bx = bias[col]; by = bias[col + 1]; }
            float2 v0 = make_float2(acc[mt][nt][0] + bx, acc[mt][nt][1] + by);
            float2 v1 = make_float2(acc[mt][nt][2] + bx, acc[mt][nt][3] + by);
            *(float2*)(C + (long long)r0g * Nreal + col) = v0;
            *(float2*)(C + (long long)(r0g + 8) * Nreal + col) = v1;
        }
    }
}

// ---------------------------------------------------------------------------
// LSTM elementwise; also writes fp16 h for the logits GEMM A side
// ---------------------------------------------------------------------------
__global__ void lstm_kernel(const float* __restrict__ b_ih,
                            const float* __restrict__ b_hh,
                            float* __restrict__ h_out,
                            float* __restrict__ c_out) {
    int idx = blockIdx.x * blockDim.x + threadIdx.x;
    if (idx >= B_*E_) return;
    int b = idx >> 10, e = idx & (E_ - 1);
    const float* g = g_gates + (long long)b * G4E_;
    float xi = g[e]        + b_ih[e]        + b_hh[e];
    float xf = g[E_   + e] + b_ih[E_   + e] + b_hh[E_   + e];
    float xg = g[2*E_ + e] + b_ih[2*E_ + e] + b_hh[2*E_ + e];
    float xo = g[3*E_ + e] + b_ih[3*E_ + e] + b_hh[3*E_ + e];
    float ig = 1.f / (1.f + __expf(-xi));
    float fg = 1.f / (1.f + __expf(-xf));
    float gg = tanhf(xg);
    float og = 1.f / (1.f + __expf(-xo));
    float c  = fg * g_ctx[idx] + ig * gg;
    float h  = og * tanhf(c);
    h_out[idx] = h;
    c_out[idx] = c;
    g_h[idx] = __float2half_rn(h);
}

// ---------------------------------------------------------------------------
extern "C" void kernel_launch(void* const* d_in, const int* in_sizes, int n_in,
                              void* d_out, int out_size) {
    const void *p_tgt=0, *p_enc=0, *p_h0=0, *p_pad=0, *p_emb=0, *p_wproj=0,
               *p_wih=0, *p_whh=0, *p_bih=0, *p_bhh=0, *p_bproj=0;
    int seen_be = 0, seen_ve = 0, seen_w = 0, seen_b4 = 0;
    for (int i = 0; i < n_in; i++) {
        long long s = in_sizes[i];
        if      (s == 512)                  p_tgt = d_in[i];
        else if (s == (long long)B_*ML_*E_) p_enc = d_in[i];
        else if (s == (long long)B_*E_)     { if (seen_be++ == 0) p_h0 = d_in[i]; }
        else if (s == B_*ML_)               p_pad = d_in[i];
        else if (s == (long long)V_*E_)     { if (seen_ve++ == 0) p_emb = d_in[i]; else p_wproj = d_in[i]; }
        else if (s == (long long)G4E_*E_)   { if (seen_w++  == 0) p_wih = d_in[i]; else p_whh = d_in[i]; }
        else if (s == G4E_)                 { if (seen_b4++ == 0) p_bih = d_in[i]; else p_bhh = d_in[i]; }
        else if (s == V_)                   p_bproj = d_in[i];
    }

    const int*   tgt    = (const int*)p_tgt;
    const float* enc    = (const float*)p_enc;
    const float* h0     = (const float*)p_h0;
    const float* emb    = (const float*)p_emb;
    const float* w_ih   = (const float*)p_wih;
    const float* w_hh   = (const float*)p_whh;
    const float* b_ih   = (const float*)p_bih;
    const float* b_hh   = (const float*)p_bhh;
    const float* w_proj = (const float*)p_wproj;
    const float* b_proj = (const float*)p_bproj;

    float* out    = (float*)d_out;
    float* logits = out;
    float* h_out  = out + (long long)B_ * V_;
    float* c_out  = h_out + (long long)B_ * E_;

    float *gates;
    cudaGetSymbolAddress((void**)&gates, g_gates);
    __half *wg, *ag, *hh;
    cudaGetSymbolAddress((void**)&wg, g_wg);
    cudaGetSymbolAddress((void**)&ag, g_ag);
    cudaGetSymbolAddress((void**)&hh, g_h);

    const int SMEM64G  = 3 * (64*128 + 16384);            // 72 KB (fp16 gates)
    const int SMEM128F = 3 * (128*64 + 128*64 + 128*128); // 96 KB (f32b logits)
    cudaFuncSetAttribute(gemm_fp16_mma<64>, cudaFuncAttributeMaxDynamicSharedMemorySize, SMEM64G);
    cudaFuncSetAttribute(gemm_f32b<128>,    cudaFuncAttributeMaxDynamicSharedMemorySize, SMEM128F);

    // 1) heterogeneous prelude: attention + wgate conversion + gather
    prelude_kernel<<<NB_TOTAL, 256>>>(enc, h0, p_pad, w_ih, w_hh, tgt, emb);

    // 2) gates GEMM: [512,2048] x [4096,2048]^T -> g_gates
    {
        dim3 gridG(B_/64, G4E_/128);
        gemm_fp16_mma<64><<<gridG, 256, SMEM64G>>>(ag, wg, gates, nullptr, KGATE, G4E_);
    }

    // 3) LSTM
    lstm_kernel<<<(B_*E_ + 255)/256, 256>>>(b_ih, b_hh, h_out, c_out);

    // 4) logits GEMM: fp16 h x fp32 w_proj (in-smem convert), no pre-pass
    {
        dim3 gridV(B_/128, (V_ + 127)/128);
        gemm_f32b<128><<<gridV, 256, SMEM128F>>>(
            hh, w_proj, E_, V_, logits, b_proj, E_, V_);
    }
}

// round 17
// speedup vs baseline: 1.0909x; 1.0143x over previous
#include <cuda_runtime.h>
#include <cuda_fp16.h>
#include <math.h>
#include <stdint.h>

#define B_    512
#define E_    1024
#define ML_   50
#define V_    50000
#define G4E_  (4*E_)
#define NPADV 50048          // V padded to multiple of 128
#define KGATE 2048           // gates K: [words|ctx] vs [w_ih|w_hh]

#define NB_ATT   B_          // prelude: attention blocks
#define NB_WG    256         // prelude: wgate-conversion blocks
#define NB_GATH  64          // prelude: gather blocks
#define NB_TOTAL (NB_ATT + NB_WG + NB_GATH)

#define NB_GEMM  256         // midlude: gates GEMM blocks (8 m x 32 n)
#define NB_WPC   256         // midlude: wproj-conversion blocks
#define NB_MID   (NB_GEMM + NB_WPC)

// ---------------- scratch (__device__ globals; allocation-free rule) --------
__device__ float g_ctx[B_*E_];
__device__ float g_gates[(long long)B_*G4E_];

__device__ __half g_wp[(long long)NPADV*E_];     // w_proj fp16 (rows >= V_ zero)
__device__ __half g_wg[(long long)G4E_*KGATE];   // [w_ih | w_hh] fp16
__device__ __half g_ag[B_*KGATE];                // [words | ctx] fp16 (GEMM A)
__device__ __half g_h[B_*E_];                    // h_new fp16 (GEMM A)

union H8 { __half h[8]; uint4 u; };

// ---------------- PTX helpers (arch-stable, sm_80-era) ----------------------
__device__ __forceinline__ uint32_t smem_u32(const void* p) {
    uint32_t a;
    asm("{ .reg .u64 t; cvta.to.shared.u64 t, %1; cvt.u32.u64 %0, t; }" : "=r"(a) : "l"(p));
    return a;
}
#define CP_ASYNC16(dst, src) \
    asm volatile("cp.async.cg.shared.global [%0], [%1], 16;" :: "r"(dst), "l"(src) : "memory")
#define CP_COMMIT() asm volatile("cp.async.commit_group;" ::: "memory")
#define CP_WAIT1()  asm volatile("cp.async.wait_group 1;" ::: "memory")
#define CP_WAIT0()  asm volatile("cp.async.wait_group 0;" ::: "memory")

__device__ __forceinline__ void ldsm_x4(uint32_t addr, uint32_t& r0, uint32_t& r1,
                                        uint32_t& r2, uint32_t& r3) {
    asm volatile("ldmatrix.sync.aligned.m8n8.x4.shared.b16 {%0,%1,%2,%3}, [%4];"
                 : "=r"(r0), "=r"(r1), "=r"(r2), "=r"(r3) : "r"(addr));
}
__device__ __forceinline__ void mma16816(float* c, const uint32_t* a, const uint32_t* b) {
    asm volatile("mma.sync.aligned.m16n8k16.row.col.f32.f16.f16.f32 "
                 "{%0,%1,%2,%3}, {%4,%5,%6,%7}, {%8,%9}, {%0,%1,%2,%3};"
                 : "+f"(c[0]), "+f"(c[1]), "+f"(c[2]), "+f"(c[3])
                 : "r"(a[0]), "r"(a[1]), "r"(a[2]), "r"(a[3]), "r"(b[0]), "r"(b[1]));
}
__device__ __forceinline__ uint32_t swz128(uint32_t o) { return o ^ ((o >> 3) & 0x70); }

// ---------------------------------------------------------------------------
// PRELUDE: attention [0,512) + wgate conversion [512,768) + gather [768,832)
// ---------------------------------------------------------------------------
__global__ void __launch_bounds__(256) prelude_kernel(
    const float* __restrict__ enc,
    const float* __restrict__ h0,
    const void* __restrict__ pad_raw,
    const float* __restrict__ w_ih,
    const float* __restrict__ w_hh,
    const int*   __restrict__ tgt,
    const float* __restrict__ emb)
{
    int tid = threadIdx.x;

    if (blockIdx.x >= NB_ATT + NB_WG) {
        const int total = B_*(E_/4);
        int start = (blockIdx.x - NB_ATT - NB_WG) * 256 + tid;
        for (int t = start; t < total; t += NB_GATH * 256) {
            int b = t / (E_/4), e4 = t % (E_/4);
            float4 v = *(const float4*)(emb + (long long)tgt[b] * E_ + e4*4);
            __half2 h01 = __floats2half2_rn(v.x, v.y);
            __half2 h23 = __floats2half2_rn(v.z, v.w);
            uint2 u = make_uint2(*(uint32_t*)&h01, *(uint32_t*)&h23);
            *(uint2*)&g_ag[b * KGATE + e4*4] = u;
        }
        return;
    }

    if (blockIdx.x >= NB_ATT) {
        const long long total = (long long)G4E_ * (KGATE/8);
        long long start = (long long)(blockIdx.x - NB_ATT) * 256 + tid;
        for (long long t = start; t < total; t += (long long)NB_WG * 256) {
            int row = (int)(t / (KGATE/8));
            int k0  = (int)(t % (KGATE/8)) * 8;
            const float* s = (k0 < E_) ? (w_ih + (long long)row*E_ + k0)
                                       : (w_hh + (long long)row*E_ + (k0 - E_));
            const float4 a = *(const float4*)s;
            const float4 b = *(const float4*)(s + 4);
            H8 hi;
            hi.h[0]=__float2half_rn(a.x); hi.h[1]=__float2half_rn(a.y);
            hi.h[2]=__float2half_rn(a.z); hi.h[3]=__float2half_rn(a.w);
            hi.h[4]=__float2half_rn(b.x); hi.h[5]=__float2half_rn(b.y);
            hi.h[6]=__float2half_rn(b.z); hi.h[7]=__float2half_rn(b.w);
            *(uint4*)&g_wg[(long long)row * KGATE + k0] = hi.u;
        }
        return;
    }

    // ---------------- attention ----------------
    int b = blockIdx.x;
    __shared__ float4 sh_h4[E_/4];
    __shared__ float  sh_w[ML_];
    __shared__ int    s_gt1, s_off4;

    if (tid == 0) { s_gt1 = 0; s_off4 = 0; }
    sh_h4[tid] = ((const float4*)(h0 + (long long)b*E_))[tid];
    __syncthreads();

    {
        const unsigned char* p8 = (const unsigned char*)pad_raw;
        int gt1 = 0, off4 = 0;
        for (int i = tid; i < B_*ML_; i += 256) {
            unsigned char v = p8[i];
            if (v > 1) gt1 = 1;
            if (v != 0 && (i & 3) != 0) off4 = 1;
        }
        if (gt1)  atomicOr(&s_gt1, 1);
        if (off4) atomicOr(&s_off4, 1);
    }

    int w = tid >> 5, lane = tid & 31;
    for (int l = w; l < ML_; l += 8) {
        const float4* row4 = (const float4*)(enc + ((long long)b*ML_ + l) * E_);
        float s = 0.f;
        #pragma unroll
        for (int j = 0; j < 8; j++) {
            float4 x = row4[lane + j*32];
            float4 h = sh_h4[lane + j*32];
            s += x.x*h.x + x.y*h.y + x.z*h.z + x.w*h.w;
        }
        #pragma unroll
        for (int o = 16; o > 0; o >>= 1) s += __shfl_down_sync(0xffffffffu, s, o);
        if (lane == 0) sh_w[l] = s;
    }
    __syncthreads();

    if (tid == 0) {
        int bm = (s_gt1 == 0 && s_off4 != 0) ? 1 : 0;
        const unsigned char* p8 = (const unsigned char*)pad_raw;
        const unsigned int*  pw = (const unsigned int*)pad_raw;
        float mx = -1e30f;
        for (int l = 0; l < ML_; l++) mx = fmaxf(mx, sh_w[l]);
        float sum = 0.f;
        for (int l = 0; l < ML_; l++) {
            bool masked = bm ? (p8[b*ML_ + l] != 0) : (pw[b*ML_ + l] != 0u);
            float v = masked ? 0.f : __expf(sh_w[l] - mx);
            sh_w[l] = v; sum += v;
        }
        float inv = 1.f / sum;
        for (int l = 0; l < ML_; l++) sh_w[l] *= inv;
    }
    __syncthreads();

    {
        const float4* base = (const float4*)enc + (long long)b*ML_*(E_/4) + tid;
        float4 acc = make_float4(0.f, 0.f, 0.f, 0.f);
        #pragma unroll 10
        for (int l = 0; l < ML_; l++) {
            float wl = sh_w[l];
            float4 v = base[l * (E_/4)];
            acc.x += wl*v.x; acc.y += wl*v.y; acc.z += wl*v.z; acc.w += wl*v.w;
        }
        *(float4*)(g_ctx + (long long)b*E_ + tid*4) = acc;
        __half2 h01 = __floats2half2_rn(acc.x, acc.y);
        __half2 h23 = __floats2half2_rn(acc.z, acc.w);
        uint2 u = make_uint2(*(uint32_t*)&h01, *(uint32_t*)&h23);
        *(uint2*)&g_ag[b * KGATE + E_ + tid*4] = u;
    }
}

// ---------------------------------------------------------------------------
// MIDLUDE: heterogeneous launch.
//   blocks [0, NB_GEMM)        : gates GEMM (BM=64, proven pipeline)
//   blocks [NB_GEMM, NB_MID)   : w_proj fp32 -> fp16 (grid-stride)
// Gates GEMM is tensor-bound, the converter DRAM-bound: co-residency
// overlaps their bottlenecks inside one grid.
// ---------------------------------------------------------------------------
__global__ void __launch_bounds__(256, 2) midlude_kernel(
    const __half* __restrict__ A2,    // g_ag
    const __half* __restrict__ B2,    // g_wg
    float* __restrict__ C,            // g_gates
    const float* __restrict__ wproj)
{
    int tid = threadIdx.x;

    if (blockIdx.x >= NB_GEMM) {
        // ---------------- wproj converter ----------------
        const long long total = (long long)NPADV * (E_/8);
        long long start = (long long)(blockIdx.x - NB_GEMM) * 256 + tid;
        for (long long t = start; t < total; t += (long long)NB_WPC * 256) {
            int row = (int)(t / (E_/8));
            int k0  = (int)(t % (E_/8)) * 8;
            H8 hi;
            if (row < V_) {
                const float4 a = *(const float4*)(wproj + (long long)row*E_ + k0);
                const float4 b = *(const float4*)(wproj + (long long)row*E_ + k0 + 4);
                hi.h[0]=__float2half_rn(a.x); hi.h[1]=__float2half_rn(a.y);
                hi.h[2]=__float2half_rn(a.z); hi.h[3]=__float2half_rn(a.w);
                hi.h[4]=__float2half_rn(b.x); hi.h[5]=__float2half_rn(b.y);
                hi.h[6]=__float2half_rn(b.z); hi.h[7]=__float2half_rn(b.w);
            } else {
                hi.u = make_uint4(0u, 0u, 0u, 0u);
            }
            *(uint4*)&g_wp[(long long)row * E_ + k0] = hi.u;
        }
        return;
    }

    // ---------------- gates GEMM, BM=64 (proven) ----------------
    constexpr int BM = 64;
    constexpr int WMW = 2, WN = 32, NT = 4;
    constexpr int ATILE = BM * 128;
    constexpr int STAGE = ATILE + 16384;
    constexpr int OPS = (BM + 128) / 32;   // 6
    constexpr int OPSA = BM * 8;           // 512
    const int K2 = KGATE, Nreal = G4E_;

    extern __shared__ char smem_raw[];
    const uint32_t smem = smem_u32(smem_raw);

    const int wid = tid >> 5, lane = tid & 31;
    const int wm = wid % WMW, wn = wid / WMW;
    const int m0 = (blockIdx.x % (B_/64)) * 64;
    const int n0 = (blockIdx.x / (B_/64)) * 128;
    const int nch = K2 >> 6;

    const __half* Abase = A2 + (long long)m0 * K2;
    const __half* Bbase = B2 + (long long)n0 * K2;

    auto issue_stage = [&](int stage, int chunk) {
        int kc = chunk * 64;
        uint32_t sbase = smem + stage * STAGE;
        #pragma unroll
        for (int j = 0; j < OPS; j++) {
            int op = tid + j * 256;
            const __half* src;
            uint32_t dst;
            if (op < OPSA) {
                int row = op >> 3, c = op & 7;
                src = Abase + (long long)row * K2 + kc + c * 8;
                dst = sbase + swz128((uint32_t)(row * 128 + c * 16));
            } else {
                int op2 = op - OPSA;
                int row = op2 >> 3, c = op2 & 7;
                src = Bbase + (long long)row * K2 + kc + c * 8;
                dst = sbase + ATILE + swz128((uint32_t)(row * 128 + c * 16));
            }
            CP_ASYNC16(dst, (const void*)src);
        }
        CP_COMMIT();
    };

    float acc[2][NT][4];
    #pragma unroll
    for (int mt = 0; mt < 2; mt++)
        #pragma unroll
        for (int nt = 0; nt < NT; nt++)
            #pragma unroll
            for (int q = 0; q < 4; q++) acc[mt][nt][q] = 0.f;

    issue_stage(0, 0);
    issue_stage(1, 1);

    const int a_row_in = lane & 15;
    const int a_chunk  = lane >> 4;
    const int b_row_in = (lane & 7) + ((lane & 16) ? 8 : 0);
    const int b_chunk  = (lane >> 3) & 1;

    for (int i = 0; i < nch; i++) {
        CP_WAIT1();
        __syncthreads();
        if (i + 2 < nch) issue_stage((i + 2) % 3, i + 2);
        else CP_COMMIT();

        uint32_t sbase = smem + (i % 3) * STAGE;
        uint32_t As = sbase, Bs = sbase + ATILE;

        #pragma unroll
        for (int ks = 0; ks < 4; ks++) {
            uint32_t a[2][4];
            #pragma unroll
            for (int mt = 0; mt < 2; mt++) {
                int row = wm * 32 + mt * 16 + a_row_in;
                int ch  = ks * 2 + a_chunk;
                ldsm_x4(As + swz128((uint32_t)(row * 128 + ch * 16)),
                        a[mt][0], a[mt][1], a[mt][2], a[mt][3]);
            }
            uint32_t b[NT][2];
            #pragma unroll
            for (int np = 0; np < NT/2; np++) {
                int row = wn * WN + np * 16 + b_row_in;
                int ch  = ks * 2 + b_chunk;
                ldsm_x4(Bs + swz128((uint32_t)(row * 128 + ch * 16)),
                        b[np*2][0], b[np*2][1], b[np*2+1][0], b[np*2+1][1]);
            }
            #pragma unroll
            for (int mt = 0; mt < 2; mt++)
                #pragma unroll
                for (int nt = 0; nt < NT; nt++)
                    mma16816(acc[mt][nt], a[mt], b[nt]);
        }
        __syncthreads();
    }
    CP_WAIT0();

    #pragma unroll
    for (int mt = 0; mt < 2; mt++) {
        int r0g = m0 + wm * 32 + mt * 16 + (lane >> 2);
        #pragma unroll
        for (int nt = 0; nt < NT; nt++) {
            int col = n0 + wn * WN + nt * 8 + (lane & 3) * 2;
            float2 v0 = make_float2(acc[mt][nt][0], acc[mt][nt][1]);
            float2 v1 = make_float2(acc[mt][nt][2], acc[mt][nt][3]);
            *(float2*)(C + (long long)r0g * Nreal + col) = v0;
            *(float2*)(C + (long long)(r0g + 8) * Nreal + col) = v1;
        }
    }
}

// ---------------------------------------------------------------------------
// fp16 GEMM via mma.sync (proven): logits = h @ wp^T + bias
// ---------------------------------------------------------------------------
template<int BM>
__global__ void __launch_bounds__(256, 2) gemm_fp16_mma(
    const __half* __restrict__ A2, const __half* __restrict__ B2,
    float* __restrict__ C, const float* __restrict__ bias,
    int K2, int Nreal)
{
    constexpr int WMW = (BM == 128) ? 4 : 2;
    constexpr int WNW = 8 / WMW;
    constexpr int WN  = 128 / WNW;
    constexpr int NT  = WN / 8;
    constexpr int ATILE = BM * 128;
    constexpr int STAGE = ATILE + 16384;
    constexpr int OPS = (BM + 128) / 32;
    constexpr int OPSA = BM * 8;

    extern __shared__ char smem_raw[];
    const uint32_t smem = smem_u32(smem_raw);

    const int tid = threadIdx.x;
    const int wid = tid >> 5, lane = tid & 31;
    const int wm = wid % WMW, wn = wid / WMW;
    const int m0 = blockIdx.x * BM, n0 = blockIdx.y * 128;
    const int nch = K2 >> 6;

    const __half* Abase = A2 + (long long)m0 * K2;
    const __half* Bbase = B2 + (long long)n0 * K2;

    auto issue_stage = [&](int stage, int chunk) {
        int kc = chunk * 64;
        uint32_t sbase = smem + stage * STAGE;
        #pragma unroll
        for (int j = 0; j < OPS; j++) {
            int op = tid + j * 256;
            const __half* src;
            uint32_t dst;
            if (op < OPSA) {
                int row = op >> 3, c = op & 7;
                src = Abase + (long long)row * K2 + kc + c * 8;
                dst = sbase + swz128((uint32_t)(row * 128 + c * 16));
            } else {
                int op2 = op - OPSA;
                int row = op2 >> 3, c = op2 & 7;
                src = Bbase + (long long)row * K2 + kc + c * 8;
                dst = sbase + ATILE + swz128((uint32_t)(row * 128 + c * 16));
            }
            CP_ASYNC16(dst, (const void*)src);
        }
        CP_COMMIT();
    };

    float acc[2][NT][4];
    #pragma unroll
    for (int mt = 0; mt < 2; mt++)
        #pragma unroll
        for (int nt = 0; nt < NT; nt++)
            #pragma unroll
            for (int q = 0; q < 4; q++) acc[mt][nt][q] = 0.f;

    issue_stage(0, 0);
    if (nch > 1) issue_stage(1, 1); else CP_COMMIT();

    const int a_row_in = lane & 15;
    const int a_chunk  = lane >> 4;
    const int b_row_in = (lane & 7) + ((lane & 16) ? 8 : 0);
    const int b_chunk  = (lane >> 3) & 1;

    for (int i = 0; i < nch; i++) {
        CP_WAIT1();
        __syncthreads();
        if (i + 2 < nch) issue_stage((i + 2) % 3, i + 2);
        else CP_COMMIT();

        uint32_t sbase = smem + (i % 3) * STAGE;
        uint32_t As = sbase, Bs = sbase + ATILE;

        #pragma unroll
        for (int ks = 0; ks < 4; ks++) {
            uint32_t a[2][4];
            #pragma unroll
            for (int mt = 0; mt < 2; mt++) {
                int row = wm * 32 + mt * 16 + a_row_in;
                int ch  = ks * 2 + a_chunk;
                ldsm_x4(As + swz128((uint32_t)(row * 128 + ch * 16)),
                        a[mt][0], a[mt][1], a[mt][2], a[mt][3]);
            }
            uint32_t b[NT][2];
            #pragma unroll
            for (int np = 0; np < NT/2; np++) {
                int row = wn * WN + np * 16 + b_row_in;
                int ch  = ks * 2 + b_chunk;
                ldsm_x4(Bs + swz128((uint32_t)(row * 128 + ch * 16)),
                        b[np*2][0], b[np*2][1], b[np*2+1][0], b[np*2+1][1]);
            }
            #pragma unroll
            for (int mt = 0; mt < 2; mt++)
                #pragma unroll
                for (int nt = 0; nt < NT; nt++)
                    mma16816(acc[mt][nt], a[mt], b[nt]);
        }
        __syncthreads();
    }
    CP_WAIT0();

    #pragma unroll
    for (int mt = 0; mt < 2; mt++) {
        int r0g = m0 + wm * 32 + mt * 16 + (lane >> 2);
        #pragma unroll
        for (int nt = 0; nt < NT; nt++) {
            int col = n0 + wn * WN + nt * 8 + (lane & 3) * 2;
            if (col >= Nreal) continue;
            float bx = 0.f, by = 0.f;
            if (bias) { bx = bias[col]; by = bias[col + 1]; }
            float2 v0 = make_float2(acc[mt][nt][0] + bx, acc[mt][nt][1] + by);
            float2 v1 = make_float2(acc[mt][nt][2] + bx, acc[mt][nt][3] + by);
            *(float2*)(C + (long long)r0g * Nreal + col) = v0;
            *(float2*)(C + (long long)(r0g + 8) * Nreal + col) = v1;
        }
    }
}

// ---------------------------------------------------------------------------
// LSTM elementwise; also writes fp16 h for the logits GEMM A side
// ---------------------------------------------------------------------------
__global__ void lstm_kernel(const float* __restrict__ b_ih,
                            const float* __restrict__ b_hh,
                            float* __restrict__ h_out,
                            float* __restrict__ c_out) {
    int idx = blockIdx.x * blockDim.x + threadIdx.x;
    if (idx >= B_*E_) return;
    int b = idx >> 10, e = idx & (E_ - 1);
    const float* g = g_gates + (long long)b * G4E_;
    float xi = g[e]        + b_ih[e]        + b_hh[e];
    float xf = g[E_   + e] + b_ih[E_   + e] + b_hh[E_   + e];
    float xg = g[2*E_ + e] + b_ih[2*E_ + e] + b_hh[2*E_ + e];
    float xo = g[3*E_ + e] + b_ih[3*E_ + e] + b_hh[3*E_ + e];
    float ig = 1.f / (1.f + __expf(-xi));
    float fg = 1.f / (1.f + __expf(-xf));
    float gg = tanhf(xg);
    float og = 1.f / (1.f + __expf(-xo));
    float c  = fg * g_ctx[idx] + ig * gg;
    float h  = og * tanhf(c);
    h_out[idx] = h;
    c_out[idx] = c;
    g_h[idx] = __float2half_rn(h);
}

// ---------------------------------------------------------------------------
extern "C" void kernel_launch(void* const* d_in, const int* in_sizes, int n_in,
                              void* d_out, int out_size) {
    const void *p_tgt=0, *p_enc=0, *p_h0=0, *p_pad=0, *p_emb=0, *p_wproj=0,
               *p_wih=0, *p_whh=0, *p_bih=0, *p_bhh=0, *p_bproj=0;
    int seen_be = 0, seen_ve = 0, seen_w = 0, seen_b4 = 0;
    for (int i = 0; i < n_in; i++) {
        long long s = in_sizes[i];
        if      (s == 512)                  p_tgt = d_in[i];
        else if (s == (long long)B_*ML_*E_) p_enc = d_in[i];
        else if (s == (long long)B_*E_)     { if (seen_be++ == 0) p_h0 = d_in[i]; }
        else if (s == B_*ML_)               p_pad = d_in[i];
        else if (s == (long long)V_*E_)     { if (seen_ve++ == 0) p_emb = d_in[i]; else p_wproj = d_in[i]; }
        else if (s == (long long)G4E_*E_)   { if (seen_w++  == 0) p_wih = d_in[i]; else p_whh = d_in[i]; }
        else if (s == G4E_)                 { if (seen_b4++ == 0) p_bih = d_in[i]; else p_bhh = d_in[i]; }
        else if (s == V_)                   p_bproj = d_in[i];
    }

    const int*   tgt    = (const int*)p_tgt;
    const float* enc    = (const float*)p_enc;
    const float* h0     = (const float*)p_h0;
    const float* emb    = (const float*)p_emb;
    const float* w_ih   = (const float*)p_wih;
    const float* w_hh   = (const float*)p_whh;
    const float* b_ih   = (const float*)p_bih;
    const float* b_hh   = (const float*)p_bhh;
    const float* w_proj = (const float*)p_wproj;
    const float* b_proj = (const float*)p_bproj;

    float* out    = (float*)d_out;
    float* logits = out;
    float* h_out  = out + (long long)B_ * V_;
    float* c_out  = h_out + (long long)B_ * E_;

    float *gates;
    cudaGetSymbolAddress((void**)&gates, g_gates);
    __half *wp, *wg, *ag, *hh;
    cudaGetSymbolAddress((void**)&wp, g_wp);
    cudaGetSymbolAddress((void**)&wg, g_wg);
    cudaGetSymbolAddress((void**)&ag, g_ag);
    cudaGetSymbolAddress((void**)&hh, g_h);

    const int SMEM64  = 3 * (64*128 + 16384);    // 72 KB (midlude gates GEMM)
    const int SMEM128 = 3 * (128*128 + 16384);   // 96 KB (logits GEMM)
    cudaFuncSetAttribute(midlude_kernel,     cudaFuncAttributeMaxDynamicSharedMemorySize, SMEM64);
    cudaFuncSetAttribute(gemm_fp16_mma<128>, cudaFuncAttributeMaxDynamicSharedMemorySize, SMEM128);

    // 1) prelude: attention + wgate conversion + gather (heterogeneous)
    prelude_kernel<<<NB_TOTAL, 256>>>(enc, h0, p_pad, w_ih, w_hh, tgt, emb);

    // 2) midlude: gates GEMM + wproj conversion (heterogeneous)
    midlude_kernel<<<NB_MID, 256, SMEM64>>>(ag, wg, gates, w_proj);

    // 3) LSTM
    lstm_kernel<<<(B_*E_ + 255)/256, 256>>>(b_ih, b_hh, h_out, c_out);

    // 4) logits GEMM (fp16 path, proven 115 us)
    {
        dim3 gridV(B_/128, NPADV/128);
        gemm_fp16_mma<128><<<gridV, 256, SMEM128>>>(
            hh, wp, logits, b_proj, E_, V_);
    }
}